// round 2
// baseline (speedup 1.0000x reference)
#include <cuda_runtime.h>
#include <cstdint>

#define NH 8
#define HD 32
#define NWIN 144
#define BNW 2048
#define DIMC 256
#define M_TOK (BNW*NWIN)          // 294912
#define QK_SCALE 0.17677669529663687f

// ---------------- scratch (alloc-free: __device__ globals) ----------------
__device__ float g_q[BNW*NH*NWIN*HD];
__device__ float g_k[BNW*NH*NWIN*HD];
__device__ float g_v[BNW*NH*NWIN*HD];
__device__ float g_attn[(size_t)M_TOK*DIMC];
__device__ float g_bias[NH*NWIN*NWIN];

// ---------------- helpers ----------------
__device__ __forceinline__ uint32_t f2tf(float f){
    uint32_t u; asm("cvt.rna.tf32.f32 %0, %1;" : "=r"(u) : "f"(f)); return u;
}
__device__ __forceinline__ float f2tff(float f){ return __uint_as_float(f2tf(f)); }

__device__ __forceinline__ void mma8(float* d,
    uint32_t a0, uint32_t a1, uint32_t a2, uint32_t a3,
    uint32_t b0, uint32_t b1)
{
    asm volatile(
      "mma.sync.aligned.m16n8k8.row.col.f32.tf32.tf32.f32 "
      "{%0,%1,%2,%3}, {%4,%5,%6,%7}, {%8,%9}, {%0,%1,%2,%3};\n"
      : "+f"(d[0]), "+f"(d[1]), "+f"(d[2]), "+f"(d[3])
      : "r"(a0), "r"(a1), "r"(a2), "r"(a3), "r"(b0), "r"(b1));
}

// ---------------- bias precompute: g_bias[h][r][c] ----------------
__global__ void bias_kernel(const float* __restrict__ rpb, const int* __restrict__ rel)
{
    int i = blockIdx.x * 256 + threadIdx.x;
    if (i < NH*NWIN*NWIN) {
        int h  = i / (NWIN*NWIN);
        int rc = i - h * (NWIN*NWIN);
        g_bias[i] = rpb[rel[rc]*NH + h];
    }
}

// ---------------- GEMM template: C[M,N] = X[M,256] * W[256,N] ----------------
// CTA tile 128x64, 8 warps (4 M x 2 N), warp tile 32x32, BK=32, tf32 mma.
// EPI==0: QKV epilogue (+qkv_b, scale q, scatter to g_q/g_k/g_v)
// EPI==1: proj epilogue (+proj_b, write out), X is g_attn
template<int N_GL, int EPI>
__global__ __launch_bounds__(256)
void gemm_kernel(const float* __restrict__ Xin, const float* __restrict__ W,
                 const float* __restrict__ bias, float* __restrict__ out)
{
    __shared__ float As[128*36];      // [m][k], stride 36
    __shared__ float Bs[32*68];       // [k][n], stride 68

    const float* X = (EPI == 1) ? (const float*)g_attn : Xin;

    const int tid  = threadIdx.x;
    const int warp = tid >> 5, lane = tid & 31;
    const int g    = lane >> 2, tig = lane & 3;
    const int wm   = warp & 3,  wn  = warp >> 2;
    const int bm   = blockIdx.y, bn = blockIdx.x;

    const float* Xg = X + (size_t)bm * 128 * 256;
    const float* Wg = W + bn * 64;

    float acc[2][4][4];
    #pragma unroll
    for (int a = 0; a < 2; a++)
      #pragma unroll
      for (int b = 0; b < 4; b++)
        #pragma unroll
        for (int c = 0; c < 4; c++) acc[a][b][c] = 0.f;

    for (int kt = 0; kt < 8; kt++) {        // K = 256 = 8 * 32
        // load A tile 128x32 -> As (tf32)
        #pragma unroll
        for (int j = 0; j < 4; j++) {
            int fidx = tid + 256*j;
            int row = fidx >> 3, c4 = fidx & 7;
            float4 v = *(const float4*)(Xg + row*256 + kt*32 + c4*4);
            float* d = &As[row*36 + c4*4];
            d[0] = f2tff(v.x); d[1] = f2tff(v.y); d[2] = f2tff(v.z); d[3] = f2tff(v.w);
        }
        // load B tile 32x64 -> Bs (tf32)
        #pragma unroll
        for (int j = 0; j < 2; j++) {
            int fidx = tid + 256*j;
            int row = fidx >> 4, c4 = fidx & 15;
            float4 v = *(const float4*)(Wg + (size_t)(kt*32 + row)*N_GL + c4*4);
            float* d = &Bs[row*68 + c4*4];
            d[0] = f2tff(v.x); d[1] = f2tff(v.y); d[2] = f2tff(v.z); d[3] = f2tff(v.w);
        }
        __syncthreads();

        #pragma unroll
        for (int kk = 0; kk < 4; kk++) {    // 4 k-steps of 8
            uint32_t a[2][4];
            #pragma unroll
            for (int mf = 0; mf < 2; mf++) {
                int rb = wm*32 + mf*16;
                a[mf][0] = __float_as_uint(As[(rb+g  )*36 + kk*8 + tig  ]);
                a[mf][1] = __float_as_uint(As[(rb+g+8)*36 + kk*8 + tig  ]);
                a[mf][2] = __float_as_uint(As[(rb+g  )*36 + kk*8 + tig+4]);
                a[mf][3] = __float_as_uint(As[(rb+g+8)*36 + kk*8 + tig+4]);
            }
            #pragma unroll
            for (int nf = 0; nf < 4; nf++) {
                int col = wn*32 + nf*8 + g;
                uint32_t b0 = __float_as_uint(Bs[(kk*8 + tig  )*68 + col]);
                uint32_t b1 = __float_as_uint(Bs[(kk*8 + tig+4)*68 + col]);
                mma8(acc[0][nf], a[0][0], a[0][1], a[0][2], a[0][3], b0, b1);
                mma8(acc[1][nf], a[1][0], a[1][1], a[1][2], a[1][3], b0, b1);
            }
        }
        __syncthreads();
    }

    // epilogue
    #pragma unroll
    for (int mf = 0; mf < 2; mf++) {
        #pragma unroll
        for (int half = 0; half < 2; half++) {
            int m = bm*128 + wm*32 + mf*16 + g + half*8;
            int w = m / NWIN;
            int t = m - w * NWIN;
            #pragma unroll
            for (int nf = 0; nf < 4; nf++) {
                #pragma unroll
                for (int e = 0; e < 2; e++) {
                    int n = bn*64 + wn*32 + nf*8 + 2*tig + e;
                    float v = acc[mf][nf][half*2 + e] + __ldg(&bias[n]);
                    if (EPI == 0) {
                        int sec = n >> 8, c = n & 255, h = c >> 5, d = c & 31;
                        float* dst = (sec == 0) ? g_q : ((sec == 1) ? g_k : g_v);
                        if (sec == 0) v *= QK_SCALE;
                        dst[(((w*NH + h)*NWIN + t) << 5) + d] = v;
                    } else {
                        out[(size_t)m*DIMC + n] = v;
                    }
                }
            }
        }
    }
}

// ---------------- attention: one CTA per (window, head) ----------------
// smem: Qs/Ks/Vs [144][36] tf32, Ps [144][148], rsum[144]
#define PS_STR 148
#define QKV_STR 36
#define SMEM_ATTN ((3*NWIN*QKV_STR + NWIN*PS_STR + NWIN) * 4)

__global__ __launch_bounds__(256)
void attn_kernel()
{
    extern __shared__ float sm[];
    float* Qs = sm;
    float* Ks = Qs + NWIN*QKV_STR;
    float* Vs = Ks + NWIN*QKV_STR;
    float* Ps = Vs + NWIN*QKV_STR;
    float* rsum = Ps + NWIN*PS_STR;

    const int tid  = threadIdx.x;
    const int warp = tid >> 5, lane = tid & 31;
    const int g    = lane >> 2, tig = lane & 3;
    const int w    = blockIdx.x >> 3;
    const int h    = blockIdx.x & 7;

    const size_t base = ((size_t)(w*NH + h)) * NWIN * HD;
    for (int idx = tid; idx < NWIN*HD; idx += 256) {
        int r = idx >> 5, d = idx & 31;
        Qs[r*QKV_STR + d] = f2tff(g_q[base + idx]);
        Ks[r*QKV_STR + d] = f2tff(g_k[base + idx]);
        Vs[r*QKV_STR + d] = f2tff(g_v[base + idx]);
    }
    __syncthreads();

    // ---- S = Q K^T + bias ----
    const float* biash = g_bias + h*NWIN*NWIN;
    for (int tile = warp; tile < 9; tile += 8) {
        int r0 = tile * 16;
        float acc[18][4];
        #pragma unroll
        for (int nf = 0; nf < 18; nf++)
            #pragma unroll
            for (int i = 0; i < 4; i++) acc[nf][i] = 0.f;

        #pragma unroll
        for (int ks = 0; ks < 4; ks++) {
            uint32_t a0 = __float_as_uint(Qs[(r0+g  )*QKV_STR + ks*8 + tig  ]);
            uint32_t a1 = __float_as_uint(Qs[(r0+g+8)*QKV_STR + ks*8 + tig  ]);
            uint32_t a2 = __float_as_uint(Qs[(r0+g  )*QKV_STR + ks*8 + tig+4]);
            uint32_t a3 = __float_as_uint(Qs[(r0+g+8)*QKV_STR + ks*8 + tig+4]);
            #pragma unroll
            for (int nf = 0; nf < 18; nf++) {
                uint32_t b0 = __float_as_uint(Ks[(nf*8+g)*QKV_STR + ks*8 + tig  ]);
                uint32_t b1 = __float_as_uint(Ks[(nf*8+g)*QKV_STR + ks*8 + tig+4]);
                mma8(acc[nf], a0, a1, a2, a3, b0, b1);
            }
        }
        #pragma unroll
        for (int nf = 0; nf < 18; nf++) {
            #pragma unroll
            for (int i = 0; i < 4; i++) {
                int r = r0 + g + ((i >> 1) << 3);
                int c = nf*8 + 2*tig + (i & 1);
                Ps[r*PS_STR + c] = acc[nf][i] + biash[r*NWIN + c];
            }
        }
    }
    __syncthreads();

    // ---- softmax rows (store exp as tf32, fold 1/sum into O epilogue) ----
    for (int rr = 0; rr < 18; rr++) {
        int r = warp*18 + rr;
        float mx = -1e30f;
        for (int c = lane; c < NWIN; c += 32) mx = fmaxf(mx, Ps[r*PS_STR + c]);
        #pragma unroll
        for (int o = 16; o > 0; o >>= 1) mx = fmaxf(mx, __shfl_xor_sync(0xffffffffu, mx, o));
        float s = 0.f;
        for (int c = lane; c < NWIN; c += 32) {
            float e = __expf(Ps[r*PS_STR + c] - mx);
            s += e;
            Ps[r*PS_STR + c] = f2tff(e);
        }
        #pragma unroll
        for (int o = 16; o > 0; o >>= 1) s += __shfl_xor_sync(0xffffffffu, s, o);
        if (lane == 0) rsum[r] = 1.0f / s;
    }
    __syncthreads();

    // ---- O = P V ----
    const size_t obase = ((size_t)w * NWIN) * DIMC + h*HD;
    for (int tile = warp; tile < 9; tile += 8) {
        int r0 = tile * 16;
        float acc[4][4];
        #pragma unroll
        for (int nf = 0; nf < 4; nf++)
            #pragma unroll
            for (int i = 0; i < 4; i++) acc[nf][i] = 0.f;

        #pragma unroll
        for (int ks = 0; ks < 18; ks++) {
            uint32_t a0 = __float_as_uint(Ps[(r0+g  )*PS_STR + ks*8 + tig  ]);
            uint32_t a1 = __float_as_uint(Ps[(r0+g+8)*PS_STR + ks*8 + tig  ]);
            uint32_t a2 = __float_as_uint(Ps[(r0+g  )*PS_STR + ks*8 + tig+4]);
            uint32_t a3 = __float_as_uint(Ps[(r0+g+8)*PS_STR + ks*8 + tig+4]);
            #pragma unroll
            for (int nf = 0; nf < 4; nf++) {
                uint32_t b0 = __float_as_uint(Vs[(ks*8 + tig  )*QKV_STR + nf*8 + g]);
                uint32_t b1 = __float_as_uint(Vs[(ks*8 + tig+4)*QKV_STR + nf*8 + g]);
                mma8(acc[nf], a0, a1, a2, a3, b0, b1);
            }
        }
        float inv0 = rsum[r0 + g];
        float inv1 = rsum[r0 + g + 8];
        #pragma unroll
        for (int nf = 0; nf < 4; nf++) {
            #pragma unroll
            for (int i = 0; i < 4; i++) {
                int r = r0 + g + ((i >> 1) << 3);
                int d = nf*8 + 2*tig + (i & 1);
                g_attn[obase + (size_t)r*DIMC + d] = acc[nf][i] * ((i >> 1) ? inv1 : inv0);
            }
        }
    }
}

// ---------------- launch ----------------
extern "C" void kernel_launch(void* const* d_in, const int* in_sizes, int n_in,
                              void* d_out, int out_size)
{
    const float* x      = (const float*)d_in[0];
    const float* qkv_w  = (const float*)d_in[1];
    const float* qkv_b  = (const float*)d_in[2];
    const float* proj_w = (const float*)d_in[3];
    const float* proj_b = (const float*)d_in[4];
    const float* rpb    = (const float*)d_in[5];
    const int*   rel    = (const int*)d_in[6];
    float*       out    = (float*)d_out;

    cudaFuncSetAttribute(attn_kernel, cudaFuncAttributeMaxDynamicSharedMemorySize, SMEM_ATTN);

    bias_kernel<<<(NH*NWIN*NWIN + 255)/256, 256>>>(rpb, rel);
    gemm_kernel<768, 0><<<dim3(12, M_TOK/128), 256>>>(x, qkv_w, qkv_b, nullptr);
    attn_kernel<<<BNW*NH, 256, SMEM_ATTN>>>();
    gemm_kernel<256, 1><<<dim3(4, M_TOK/128), 256>>>(nullptr, proj_w, proj_b, out);
}

// round 3
// speedup vs baseline: 2.2456x; 2.2456x over previous
#include <cuda_runtime.h>
#include <cstdint>

#define NH 8
#define HD 32
#define NWIN 144
#define BNW 2048
#define DIMC 256
#define M_TOK (BNW*NWIN)          // 294912
#define QK_SCALE 0.17677669529663687f

// ---------------- scratch (alloc-free: __device__ globals) ----------------
__device__ float g_q[BNW*NH*NWIN*HD];
__device__ float g_k[BNW*NH*NWIN*HD];
__device__ float g_v[BNW*NH*NWIN*HD];
__device__ float g_attn[(size_t)M_TOK*DIMC];
__device__ float g_bias[NH*NWIN*NWIN];

// ---------------- helpers ----------------
__device__ __forceinline__ uint32_t f2tf(float f){
    uint32_t u; asm("cvt.rna.tf32.f32 %0, %1;" : "=r"(u) : "f"(f)); return u;
}
__device__ __forceinline__ float f2tff(float f){ return __uint_as_float(f2tf(f)); }

__device__ __forceinline__ void mma8(float* d,
    uint32_t a0, uint32_t a1, uint32_t a2, uint32_t a3,
    uint32_t b0, uint32_t b1)
{
    asm volatile(
      "mma.sync.aligned.m16n8k8.row.col.f32.tf32.tf32.f32 "
      "{%0,%1,%2,%3}, {%4,%5,%6,%7}, {%8,%9}, {%0,%1,%2,%3};\n"
      : "+f"(d[0]), "+f"(d[1]), "+f"(d[2]), "+f"(d[3])
      : "r"(a0), "r"(a1), "r"(a2), "r"(a3), "r"(b0), "r"(b1));
}

__device__ __forceinline__ void cp16(void* s, const void* g){
    uint32_t sa = (uint32_t)__cvta_generic_to_shared(s);
    asm volatile("cp.async.cg.shared.global [%0], [%1], 16;\n" :: "r"(sa), "l"(g));
}
#define CP_COMMIT() asm volatile("cp.async.commit_group;\n")
template<int N> __device__ __forceinline__ void cp_wait(){
    asm volatile("cp.async.wait_group %0;\n" :: "n"(N));
}

// ---------------- bias precompute: g_bias[h][r][c] ----------------
__global__ void bias_kernel(const float* __restrict__ rpb, const int* __restrict__ rel)
{
    int i = blockIdx.x * 256 + threadIdx.x;
    if (i < NH*NWIN*NWIN) {
        int h  = i / (NWIN*NWIN);
        int rc = i - h * (NWIN*NWIN);
        g_bias[i] = rpb[rel[rc]*NH + h];
    }
}

// ---------------- GEMM: C[M,N] = X[M,256] * W[256,N] ----------------
// CTA tile 256x128, 8 warps (4M x 2N), warp tile 64x64, BK=32.
// cp.async double-buffered staging of raw fp32; tf32 cvt on fragment read.
// EPI==0: QKV epilogue (+qkv_b, scale q, scatter to g_q/g_k/g_v)
// EPI==1: proj epilogue (+proj_b, write out), X is g_attn
#define AS_ELE (256*36)
#define BS_ELE (32*132)
#define GM_STG (AS_ELE + BS_ELE)        // 13440 floats per stage
#define GM_SMEM (2*GM_STG*4)            // 107520 bytes

template<int N_GL, int EPI>
__global__ __launch_bounds__(256)
void gemm_kernel(const float* __restrict__ Xin, const float* __restrict__ W,
                 const float* __restrict__ bias, float* __restrict__ out)
{
    extern __shared__ float smg[];
    const float* X = (EPI == 1) ? (const float*)g_attn : Xin;

    const int tid  = threadIdx.x;
    const int warp = tid >> 5, lane = tid & 31;
    const int g    = lane >> 2, tig = lane & 3;
    const int wm   = warp & 3,  wn  = warp >> 2;
    const int bm   = blockIdx.y, bn = blockIdx.x;

    const float* Xg = X + (size_t)bm * 256 * 256;
    const float* Wg = W + bn * 128;

    float acc[4][8][4];
    #pragma unroll
    for (int a = 0; a < 4; a++)
      #pragma unroll
      for (int b = 0; b < 8; b++)
        #pragma unroll
        for (int c = 0; c < 4; c++) acc[a][b][c] = 0.f;

    // stage loader: A tile 256x32, B tile 32x128 (raw fp32)
    auto stage = [&](int kt, int buf) {
        float* As = smg + buf * GM_STG;
        float* Bs = As + AS_ELE;
        #pragma unroll
        for (int j = 0; j < 8; j++) {
            int f = tid + 256*j; int row = f >> 3, c4 = f & 7;
            cp16(&As[row*36 + c4*4], Xg + row*256 + kt*32 + c4*4);
        }
        #pragma unroll
        for (int j = 0; j < 4; j++) {
            int f = tid + 256*j; int row = f >> 5, c4 = f & 31;
            cp16(&Bs[row*132 + c4*4], Wg + (size_t)(kt*32 + row)*N_GL + c4*4);
        }
    };

    stage(0, 0); CP_COMMIT();

    for (int kt = 0; kt < 8; kt++) {        // K = 256 = 8 * 32
        if (kt < 7) { stage(kt+1, (kt+1)&1); CP_COMMIT(); cp_wait<1>(); }
        else        { cp_wait<0>(); }
        __syncthreads();

        const float* As = smg + (kt&1) * GM_STG;
        const float* Bs = As + AS_ELE;

        #pragma unroll
        for (int kk = 0; kk < 4; kk++) {
            uint32_t a[4][4];
            #pragma unroll
            for (int mf = 0; mf < 4; mf++) {
                int rb = wm*64 + mf*16;
                a[mf][0] = f2tf(As[(rb+g  )*36 + kk*8 + tig  ]);
                a[mf][1] = f2tf(As[(rb+g+8)*36 + kk*8 + tig  ]);
                a[mf][2] = f2tf(As[(rb+g  )*36 + kk*8 + tig+4]);
                a[mf][3] = f2tf(As[(rb+g+8)*36 + kk*8 + tig+4]);
            }
            #pragma unroll
            for (int nf = 0; nf < 8; nf++) {
                int col = wn*64 + nf*8 + g;
                uint32_t b0 = f2tf(Bs[(kk*8 + tig  )*132 + col]);
                uint32_t b1 = f2tf(Bs[(kk*8 + tig+4)*132 + col]);
                #pragma unroll
                for (int mf = 0; mf < 4; mf++)
                    mma8(acc[mf][nf], a[mf][0], a[mf][1], a[mf][2], a[mf][3], b0, b1);
            }
        }
        __syncthreads();
    }

    // epilogue
    #pragma unroll
    for (int mf = 0; mf < 4; mf++) {
        #pragma unroll
        for (int half = 0; half < 2; half++) {
            int m = bm*256 + wm*64 + mf*16 + g + half*8;
            int w = m / NWIN;
            int t = m - w * NWIN;
            #pragma unroll
            for (int nf = 0; nf < 8; nf++) {
                #pragma unroll
                for (int e = 0; e < 2; e++) {
                    int n = bn*128 + wn*64 + nf*8 + 2*tig + e;
                    float v = acc[mf][nf][half*2 + e] + __ldg(&bias[n]);
                    if (EPI == 0) {
                        int sec = n >> 8, c = n & 255, h = c >> 5, d = c & 31;
                        float* dst = (sec == 0) ? g_q : ((sec == 1) ? g_k : g_v);
                        if (sec == 0) v *= QK_SCALE;
                        dst[(((w*NH + h)*NWIN + t) << 5) + d] = v;
                    } else {
                        out[(size_t)m*DIMC + n] = v;
                    }
                }
            }
        }
    }
}

// ---------------- attention: one CTA per (window, head), 9 warps ----------------
// Each warp owns exactly one 16-row tile. Softmax fully in registers
// (C-fragment quad = full 144-col row). smem: Q/K/V [144][36] tf32, P [144][148] tf32.
#define PS_STR 148
#define QKV_STR 36
#define SMEM_ATTN ((3*NWIN*QKV_STR + NWIN*PS_STR) * 4)   // 147456 B

__global__ __launch_bounds__(288)
void attn_kernel()
{
    extern __shared__ float sm[];
    float* Qs = sm;
    float* Ks = Qs + NWIN*QKV_STR;
    float* Vs = Ks + NWIN*QKV_STR;
    float* Ps = Vs + NWIN*QKV_STR;

    const int tid  = threadIdx.x;
    const int warp = tid >> 5, lane = tid & 31;
    const int g    = lane >> 2, tig = lane & 3;
    const int w    = blockIdx.x >> 3;
    const int h    = blockIdx.x & 7;

    const size_t base = ((size_t)(w*NH + h)) * NWIN * HD;
    #pragma unroll
    for (int it = 0; it < 4; it++) {
        int i4 = tid + it*288;              // 4*288 = 1152 = 144*32/4
        int r = i4 >> 3, d = (i4 & 7) << 2;
        float4 q = *(const float4*)(g_q + base + ((size_t)i4 << 2));
        float4 k = *(const float4*)(g_k + base + ((size_t)i4 << 2));
        float4 v = *(const float4*)(g_v + base + ((size_t)i4 << 2));
        float* dq = &Qs[r*QKV_STR + d];
        dq[0]=f2tff(q.x); dq[1]=f2tff(q.y); dq[2]=f2tff(q.z); dq[3]=f2tff(q.w);
        float* dk = &Ks[r*QKV_STR + d];
        dk[0]=f2tff(k.x); dk[1]=f2tff(k.y); dk[2]=f2tff(k.z); dk[3]=f2tff(k.w);
        float* dv = &Vs[r*QKV_STR + d];
        dv[0]=f2tff(v.x); dv[1]=f2tff(v.y); dv[2]=f2tff(v.z); dv[3]=f2tff(v.w);
    }
    __syncthreads();

    const int r0 = warp * 16;

    // ---- S = Q K^T (16 x 144 per warp) ----
    float acc[18][4];
    #pragma unroll
    for (int nf = 0; nf < 18; nf++)
        #pragma unroll
        for (int i = 0; i < 4; i++) acc[nf][i] = 0.f;

    #pragma unroll
    for (int ks = 0; ks < 4; ks++) {
        uint32_t a0 = __float_as_uint(Qs[(r0+g  )*QKV_STR + ks*8 + tig  ]);
        uint32_t a1 = __float_as_uint(Qs[(r0+g+8)*QKV_STR + ks*8 + tig  ]);
        uint32_t a2 = __float_as_uint(Qs[(r0+g  )*QKV_STR + ks*8 + tig+4]);
        uint32_t a3 = __float_as_uint(Qs[(r0+g+8)*QKV_STR + ks*8 + tig+4]);
        #pragma unroll
        for (int nf = 0; nf < 18; nf++) {
            uint32_t b0 = __float_as_uint(Ks[(nf*8+g)*QKV_STR + ks*8 + tig  ]);
            uint32_t b1 = __float_as_uint(Ks[(nf*8+g)*QKV_STR + ks*8 + tig+4]);
            mma8(acc[nf], a0, a1, a2, a3, b0, b1);
        }
    }

    // ---- bias add + register softmax ----
    // Row r0+g lives in the 4 lanes of this quad: full-row reduce = 2 shfl_xor.
    const float* biash = g_bias + h*NWIN*NWIN;
    float mx0 = -1e30f, mx1 = -1e30f;
    #pragma unroll
    for (int nf = 0; nf < 18; nf++) {
        float2 b0 = *(const float2*)(biash + (r0+g  )*NWIN + nf*8 + 2*tig);
        float2 b1 = *(const float2*)(biash + (r0+g+8)*NWIN + nf*8 + 2*tig);
        acc[nf][0] += b0.x; acc[nf][1] += b0.y;
        acc[nf][2] += b1.x; acc[nf][3] += b1.y;
        mx0 = fmaxf(mx0, fmaxf(acc[nf][0], acc[nf][1]));
        mx1 = fmaxf(mx1, fmaxf(acc[nf][2], acc[nf][3]));
    }
    mx0 = fmaxf(mx0, __shfl_xor_sync(0xffffffffu, mx0, 1));
    mx0 = fmaxf(mx0, __shfl_xor_sync(0xffffffffu, mx0, 2));
    mx1 = fmaxf(mx1, __shfl_xor_sync(0xffffffffu, mx1, 1));
    mx1 = fmaxf(mx1, __shfl_xor_sync(0xffffffffu, mx1, 2));

    float s0 = 0.f, s1 = 0.f;
    #pragma unroll
    for (int nf = 0; nf < 18; nf++) {
        float e0 = __expf(acc[nf][0] - mx0);
        float e1 = __expf(acc[nf][1] - mx0);
        float e2 = __expf(acc[nf][2] - mx1);
        float e3 = __expf(acc[nf][3] - mx1);
        s0 += e0 + e1; s1 += e2 + e3;
        *(float2*)&Ps[(r0+g  )*PS_STR + nf*8 + 2*tig] = make_float2(f2tff(e0), f2tff(e1));
        *(float2*)&Ps[(r0+g+8)*PS_STR + nf*8 + 2*tig] = make_float2(f2tff(e2), f2tff(e3));
    }
    s0 += __shfl_xor_sync(0xffffffffu, s0, 1);
    s0 += __shfl_xor_sync(0xffffffffu, s0, 2);
    s1 += __shfl_xor_sync(0xffffffffu, s1, 1);
    s1 += __shfl_xor_sync(0xffffffffu, s1, 2);
    float inv0 = 1.0f / s0, inv1 = 1.0f / s1;

    // Only this warp reads its own P rows — warp-level ordering suffices.
    __syncwarp();

    // ---- O = P V (16 x 32 per warp) ----
    float o[4][4];
    #pragma unroll
    for (int nf = 0; nf < 4; nf++)
        #pragma unroll
        for (int i = 0; i < 4; i++) o[nf][i] = 0.f;

    #pragma unroll
    for (int ks = 0; ks < 18; ks++) {
        uint32_t a0 = __float_as_uint(Ps[(r0+g  )*PS_STR + ks*8 + tig  ]);
        uint32_t a1 = __float_as_uint(Ps[(r0+g+8)*PS_STR + ks*8 + tig  ]);
        uint32_t a2 = __float_as_uint(Ps[(r0+g  )*PS_STR + ks*8 + tig+4]);
        uint32_t a3 = __float_as_uint(Ps[(r0+g+8)*PS_STR + ks*8 + tig+4]);
        #pragma unroll
        for (int nf = 0; nf < 4; nf++) {
            uint32_t b0 = __float_as_uint(Vs[(ks*8 + tig  )*QKV_STR + nf*8 + g]);
            uint32_t b1 = __float_as_uint(Vs[(ks*8 + tig+4)*QKV_STR + nf*8 + g]);
            mma8(o[nf], a0, a1, a2, a3, b0, b1);
        }
    }

    const size_t obase = ((size_t)w * NWIN) * DIMC + h*HD;
    #pragma unroll
    for (int nf = 0; nf < 4; nf++) {
        int d = nf*8 + 2*tig;
        *(float2*)&g_attn[obase + (size_t)(r0+g  )*DIMC + d] =
            make_float2(o[nf][0]*inv0, o[nf][1]*inv0);
        *(float2*)&g_attn[obase + (size_t)(r0+g+8)*DIMC + d] =
            make_float2(o[nf][2]*inv1, o[nf][3]*inv1);
    }
}

// ---------------- launch ----------------
extern "C" void kernel_launch(void* const* d_in, const int* in_sizes, int n_in,
                              void* d_out, int out_size)
{
    const float* x      = (const float*)d_in[0];
    const float* qkv_w  = (const float*)d_in[1];
    const float* qkv_b  = (const float*)d_in[2];
    const float* proj_w = (const float*)d_in[3];
    const float* proj_b = (const float*)d_in[4];
    const float* rpb    = (const float*)d_in[5];
    const int*   rel    = (const int*)d_in[6];
    float*       out    = (float*)d_out;

    cudaFuncSetAttribute(gemm_kernel<768,0>, cudaFuncAttributeMaxDynamicSharedMemorySize, GM_SMEM);
    cudaFuncSetAttribute(gemm_kernel<256,1>, cudaFuncAttributeMaxDynamicSharedMemorySize, GM_SMEM);
    cudaFuncSetAttribute(attn_kernel, cudaFuncAttributeMaxDynamicSharedMemorySize, SMEM_ATTN);

    bias_kernel<<<(NH*NWIN*NWIN + 255)/256, 256>>>(rpb, rel);
    gemm_kernel<768, 0><<<dim3(6, M_TOK/256), 256, GM_SMEM>>>(x, qkv_w, qkv_b, nullptr);
    attn_kernel<<<BNW*NH, 288, SMEM_ATTN>>>();
    gemm_kernel<256, 1><<<dim3(2, M_TOK/256), 256, GM_SMEM>>>(nullptr, proj_w, proj_b, out);
}

// round 8
// speedup vs baseline: 2.7890x; 1.2420x over previous
#include <cuda_runtime.h>
#include <cstdint>

#define NH 8
#define HD 32
#define NWIN 144
#define BNW 2048
#define DIMC 256
#define M_TOK (BNW*NWIN)          // 294912
#define QK_SCALE 0.17677669529663687f

// ---------------- scratch (alloc-free: __device__ globals) ----------------
__device__ float g_q[BNW*NH*NWIN*HD];
__device__ float g_k[BNW*NH*NWIN*HD];
__device__ float g_v[BNW*NH*NWIN*HD];
__device__ float g_attn[(size_t)M_TOK*DIMC];
__device__ float g_bias[NH*NWIN*NWIN];

// ---------------- helpers ----------------
__device__ __forceinline__ uint32_t f2tf(float f){
    uint32_t u; asm("cvt.rna.tf32.f32 %0, %1;" : "=r"(u) : "f"(f)); return u;
}
__device__ __forceinline__ float f2tff(float f){ return __uint_as_float(f2tf(f)); }

__device__ __forceinline__ void mma8(float* d,
    uint32_t a0, uint32_t a1, uint32_t a2, uint32_t a3,
    uint32_t b0, uint32_t b1)
{
    asm volatile(
      "mma.sync.aligned.m16n8k8.row.col.f32.tf32.tf32.f32 "
      "{%0,%1,%2,%3}, {%4,%5,%6,%7}, {%8,%9}, {%0,%1,%2,%3};\n"
      : "+f"(d[0]), "+f"(d[1]), "+f"(d[2]), "+f"(d[3])
      : "r"(a0), "r"(a1), "r"(a2), "r"(a3), "r"(b0), "r"(b1));
}

__device__ __forceinline__ void cp16(void* s, const void* g){
    uint32_t sa = (uint32_t)__cvta_generic_to_shared(s);
    asm volatile("cp.async.cg.shared.global [%0], [%1], 16;\n" :: "r"(sa), "l"(g));
}
#define CP_COMMIT() asm volatile("cp.async.commit_group;\n")
template<int N> __device__ __forceinline__ void cp_wait(){
    asm volatile("cp.async.wait_group %0;\n" :: "n"(N));
}

// ---------------- bias precompute: g_bias[h][r][c] ----------------
__global__ void bias_kernel(const float* __restrict__ rpb, const int* __restrict__ rel)
{
    int i = blockIdx.x * 256 + threadIdx.x;
    if (i < NH*NWIN*NWIN) {
        int h  = i / (NWIN*NWIN);
        int rc = i - h * (NWIN*NWIN);
        g_bias[i] = rpb[rel[rc]*NH + h];
    }
}

// ---------------- GEMM: C[M,N] = X[M,256] * W[256,N] ----------------
// CTA tile 256x128, 8 warps (4M x 2N), warp tile 64x64, BK=32.
// 3-stage cp.async pipeline, ONE __syncthreads per K-tile.
// EPI==0: QKV epilogue (+qkv_b, scale q, scatter to g_q/g_k/g_v)
// EPI==1: proj epilogue (+proj_b, write out), X is g_attn
#define AS_ELE (256*36)
#define BS_ELE (32*132)
#define GM_STG (AS_ELE + BS_ELE)        // 13440 floats per stage
#define GM_SMEM (3*GM_STG*4)            // 161280 bytes

template<int N_GL, int EPI>
__global__ __launch_bounds__(256)
void gemm_kernel(const float* __restrict__ Xin, const float* __restrict__ W,
                 const float* __restrict__ bias, float* __restrict__ out)
{
    extern __shared__ float smg[];
    const float* X = (EPI == 1) ? (const float*)g_attn : Xin;

    const int tid  = threadIdx.x;
    const int warp = tid >> 5, lane = tid & 31;
    const int g    = lane >> 2, tig = lane & 3;
    const int wm   = warp & 3,  wn  = warp >> 2;
    const int bm   = blockIdx.y, bn = blockIdx.x;

    const float* Xg = X + (size_t)bm * 256 * 256;
    const float* Wg = W + bn * 128;

    float acc[4][8][4];
    #pragma unroll
    for (int a = 0; a < 4; a++)
      #pragma unroll
      for (int b = 0; b < 8; b++)
        #pragma unroll
        for (int c = 0; c < 4; c++) acc[a][b][c] = 0.f;

    // stage loader: A tile 256x32, B tile 32x128 (raw fp32)
    auto stage = [&](int kt, int buf) {
        float* As = smg + buf * GM_STG;
        float* Bs = As + AS_ELE;
        #pragma unroll
        for (int j = 0; j < 8; j++) {
            int f = tid + 256*j; int row = f >> 3, c4 = f & 7;
            cp16(&As[row*36 + c4*4], Xg + row*256 + kt*32 + c4*4);
        }
        #pragma unroll
        for (int j = 0; j < 4; j++) {
            int f = tid + 256*j; int row = f >> 5, c4 = f & 31;
            cp16(&Bs[row*132 + c4*4], Wg + (size_t)(kt*32 + row)*N_GL + c4*4);
        }
    };

    stage(0, 0); CP_COMMIT();
    stage(1, 1); CP_COMMIT();

    for (int kt = 0; kt < 8; kt++) {        // K = 256 = 8 * 32
        cp_wait<1>();          // stage kt resident (kt+1 may be in flight)
        __syncthreads();       // everyone done reading buffer (kt+2)%3 (iter kt-1)
        if (kt + 2 < 8) { stage(kt+2, (kt+2)%3); CP_COMMIT(); }

        const float* As = smg + (kt%3) * GM_STG;
        const float* Bs = As + AS_ELE;

        #pragma unroll
        for (int kk = 0; kk < 4; kk++) {
            uint32_t a[4][4];
            #pragma unroll
            for (int mf = 0; mf < 4; mf++) {
                int rb = wm*64 + mf*16;
                a[mf][0] = f2tf(As[(rb+g  )*36 + kk*8 + tig  ]);
                a[mf][1] = f2tf(As[(rb+g+8)*36 + kk*8 + tig  ]);
                a[mf][2] = f2tf(As[(rb+g  )*36 + kk*8 + tig+4]);
                a[mf][3] = f2tf(As[(rb+g+8)*36 + kk*8 + tig+4]);
            }
            #pragma unroll
            for (int nf = 0; nf < 8; nf++) {
                int col = wn*64 + nf*8 + g;
                uint32_t b0 = f2tf(Bs[(kk*8 + tig  )*132 + col]);
                uint32_t b1 = f2tf(Bs[(kk*8 + tig+4)*132 + col]);
                #pragma unroll
                for (int mf = 0; mf < 4; mf++)
                    mma8(acc[mf][nf], a[mf][0], a[mf][1], a[mf][2], a[mf][3], b0, b1);
            }
        }
    }

    // epilogue (float2 stores: n, n+1 are d, d+1 within same head/section)
    #pragma unroll
    for (int mf = 0; mf < 4; mf++) {
        #pragma unroll
        for (int half = 0; half < 2; half++) {
            int m = bm*256 + wm*64 + mf*16 + g + half*8;
            int w = m / NWIN;
            int t = m - w * NWIN;
            #pragma unroll
            for (int nf = 0; nf < 8; nf++) {
                int n = bn*128 + wn*64 + nf*8 + 2*tig;
                float2 bb = *(const float2*)(bias + n);
                float v0 = acc[mf][nf][half*2    ] + bb.x;
                float v1 = acc[mf][nf][half*2 + 1] + bb.y;
                if (EPI == 0) {
                    int sec = n >> 8, c = n & 255, h = c >> 5, d = c & 31;
                    float* dst = (sec == 0) ? g_q : ((sec == 1) ? g_k : g_v);
                    if (sec == 0) { v0 *= QK_SCALE; v1 *= QK_SCALE; }
                    *(float2*)&dst[(((w*NH + h)*NWIN + t) << 5) + d] = make_float2(v0, v1);
                } else {
                    *(float2*)&out[(size_t)m*DIMC + n] = make_float2(v0, v1);
                }
            }
        }
    }
}

// ---------------- attention: one CTA per (window, head), 9 warps ----------------
// Each warp owns one 16-row tile. Softmax in registers; P never touches smem:
// S C-fragment -> O A-fragment via intra-quad shfl permutation.
// smem: Q/K/V [144][36] tf32 only = 62208 B -> 2 CTAs/SM.
#define QKV_STR 36
#define SMEM_ATTN (3*NWIN*QKV_STR*4)   // 62208 B

__global__ __launch_bounds__(288, 2)
void attn_kernel()
{
    extern __shared__ float sm[];
    float* Qs = sm;
    float* Ks = Qs + NWIN*QKV_STR;
    float* Vs = Ks + NWIN*QKV_STR;

    const int tid  = threadIdx.x;
    const int warp = tid >> 5, lane = tid & 31;
    const int g    = lane >> 2, tig = lane & 3;
    const int w    = blockIdx.x >> 3;
    const int h    = blockIdx.x & 7;

    const size_t base = ((size_t)(w*NH + h)) * NWIN * HD;
    #pragma unroll
    for (int it = 0; it < 4; it++) {
        int i4 = tid + it*288;              // 4*288 = 1152 = 144*32/4
        int r = i4 >> 3, d = (i4 & 7) << 2;
        float4 q = *(const float4*)(g_q + base + ((size_t)i4 << 2));
        float4 k = *(const float4*)(g_k + base + ((size_t)i4 << 2));
        float4 v = *(const float4*)(g_v + base + ((size_t)i4 << 2));
        float* dq = &Qs[r*QKV_STR + d];
        dq[0]=f2tff(q.x); dq[1]=f2tff(q.y); dq[2]=f2tff(q.z); dq[3]=f2tff(q.w);
        float* dk = &Ks[r*QKV_STR + d];
        dk[0]=f2tff(k.x); dk[1]=f2tff(k.y); dk[2]=f2tff(k.z); dk[3]=f2tff(k.w);
        float* dv = &Vs[r*QKV_STR + d];
        dv[0]=f2tff(v.x); dv[1]=f2tff(v.y); dv[2]=f2tff(v.z); dv[3]=f2tff(v.w);
    }
    __syncthreads();

    const int r0 = warp * 16;

    // ---- S = Q K^T (16 x 144 per warp) ----
    float acc[18][4];
    #pragma unroll
    for (int nf = 0; nf < 18; nf++)
        #pragma unroll
        for (int i = 0; i < 4; i++) acc[nf][i] = 0.f;

    #pragma unroll
    for (int ks = 0; ks < 4; ks++) {
        uint32_t a0 = __float_as_uint(Qs[(r0+g  )*QKV_STR + ks*8 + tig  ]);
        uint32_t a1 = __float_as_uint(Qs[(r0+g+8)*QKV_STR + ks*8 + tig  ]);
        uint32_t a2 = __float_as_uint(Qs[(r0+g  )*QKV_STR + ks*8 + tig+4]);
        uint32_t a3 = __float_as_uint(Qs[(r0+g+8)*QKV_STR + ks*8 + tig+4]);
        #pragma unroll
        for (int nf = 0; nf < 18; nf++) {
            uint32_t b0 = __float_as_uint(Ks[(nf*8+g)*QKV_STR + ks*8 + tig  ]);
            uint32_t b1 = __float_as_uint(Ks[(nf*8+g)*QKV_STR + ks*8 + tig+4]);
            mma8(acc[nf], a0, a1, a2, a3, b0, b1);
        }
    }

    // ---- bias add + register softmax ----
    const float* biash = g_bias + h*NWIN*NWIN;
    float mx0 = -1e30f, mx1 = -1e30f;
    #pragma unroll
    for (int nf = 0; nf < 18; nf++) {
        float2 b0 = *(const float2*)(biash + (r0+g  )*NWIN + nf*8 + 2*tig);
        float2 b1 = *(const float2*)(biash + (r0+g+8)*NWIN + nf*8 + 2*tig);
        acc[nf][0] += b0.x; acc[nf][1] += b0.y;
        acc[nf][2] += b1.x; acc[nf][3] += b1.y;
        mx0 = fmaxf(mx0, fmaxf(acc[nf][0], acc[nf][1]));
        mx1 = fmaxf(mx1, fmaxf(acc[nf][2], acc[nf][3]));
    }
    mx0 = fmaxf(mx0, __shfl_xor_sync(0xffffffffu, mx0, 1));
    mx0 = fmaxf(mx0, __shfl_xor_sync(0xffffffffu, mx0, 2));
    mx1 = fmaxf(mx1, __shfl_xor_sync(0xffffffffu, mx1, 1));
    mx1 = fmaxf(mx1, __shfl_xor_sync(0xffffffffu, mx1, 2));

    float s0 = 0.f, s1 = 0.f;
    #pragma unroll
    for (int nf = 0; nf < 18; nf++) {
        float e0 = __expf(acc[nf][0] - mx0);
        float e1 = __expf(acc[nf][1] - mx0);
        float e2 = __expf(acc[nf][2] - mx1);
        float e3 = __expf(acc[nf][3] - mx1);
        s0 += e0 + e1; s1 += e2 + e3;
        acc[nf][0] = __uint_as_float(f2tf(e0));
        acc[nf][1] = __uint_as_float(f2tf(e1));
        acc[nf][2] = __uint_as_float(f2tf(e2));
        acc[nf][3] = __uint_as_float(f2tf(e3));
    }
    s0 += __shfl_xor_sync(0xffffffffu, s0, 1);
    s0 += __shfl_xor_sync(0xffffffffu, s0, 2);
    s1 += __shfl_xor_sync(0xffffffffu, s1, 1);
    s1 += __shfl_xor_sync(0xffffffffu, s1, 2);
    float inv0 = 1.0f / s0, inv1 = 1.0f / s1;

    // ---- O = P V (16 x 32 per warp); P A-frags via intra-quad shfl ----
    float o[4][4];
    #pragma unroll
    for (int nf = 0; nf < 4; nf++)
        #pragma unroll
        for (int i = 0; i < 4; i++) o[nf][i] = 0.f;

    const int sA = (lane & ~3) | (tig >> 1);   // 4g + tig/2
    const int sB = sA + 2;
    const bool odd = (tig & 1);

    #pragma unroll
    for (int ks = 0; ks < 18; ks++) {
        // A-frag: a0=P[g][8ks+tig], a1=P[g+8][8ks+tig], a2=P[g][8ks+tig+4], a3=P[g+8][8ks+tig+4]
        float p0 = __shfl_sync(0xffffffffu, acc[ks][0], sA);
        float p1 = __shfl_sync(0xffffffffu, acc[ks][1], sA);
        float p2 = __shfl_sync(0xffffffffu, acc[ks][2], sA);
        float p3 = __shfl_sync(0xffffffffu, acc[ks][3], sA);
        float q0 = __shfl_sync(0xffffffffu, acc[ks][0], sB);
        float q1 = __shfl_sync(0xffffffffu, acc[ks][1], sB);
        float q2 = __shfl_sync(0xffffffffu, acc[ks][2], sB);
        float q3 = __shfl_sync(0xffffffffu, acc[ks][3], sB);
        uint32_t a0 = __float_as_uint(odd ? p1 : p0);
        uint32_t a1 = __float_as_uint(odd ? p3 : p2);
        uint32_t a2 = __float_as_uint(odd ? q1 : q0);
        uint32_t a3 = __float_as_uint(odd ? q3 : q2);
        #pragma unroll
        for (int nf = 0; nf < 4; nf++) {
            uint32_t b0 = __float_as_uint(Vs[(ks*8 + tig  )*QKV_STR + nf*8 + g]);
            uint32_t b1 = __float_as_uint(Vs[(ks*8 + tig+4)*QKV_STR + nf*8 + g]);
            mma8(o[nf], a0, a1, a2, a3, b0, b1);
        }
    }

    const size_t obase = ((size_t)w * NWIN) * DIMC + h*HD;
    #pragma unroll
    for (int nf = 0; nf < 4; nf++) {
        int d = nf*8 + 2*tig;
        *(float2*)&g_attn[obase + (size_t)(r0+g  )*DIMC + d] =
            make_float2(o[nf][0]*inv0, o[nf][1]*inv0);
        *(float2*)&g_attn[obase + (size_t)(r0+g+8)*DIMC + d] =
            make_float2(o[nf][2]*inv1, o[nf][3]*inv1);
    }
}

// ---------------- launch ----------------
extern "C" void kernel_launch(void* const* d_in, const int* in_sizes, int n_in,
                              void* d_out, int out_size)
{
    const float* x      = (const float*)d_in[0];
    const float* qkv_w  = (const float*)d_in[1];
    const float* qkv_b  = (const float*)d_in[2];
    const float* proj_w = (const float*)d_in[3];
    const float* proj_b = (const float*)d_in[4];
    const float* rpb    = (const float*)d_in[5];
    const int*   rel    = (const int*)d_in[6];
    float*       out    = (float*)d_out;

    cudaFuncSetAttribute(gemm_kernel<768,0>, cudaFuncAttributeMaxDynamicSharedMemorySize, GM_SMEM);
    cudaFuncSetAttribute(gemm_kernel<256,1>, cudaFuncAttributeMaxDynamicSharedMemorySize, GM_SMEM);
    cudaFuncSetAttribute(attn_kernel, cudaFuncAttributeMaxDynamicSharedMemorySize, SMEM_ATTN);

    bias_kernel<<<(NH*NWIN*NWIN + 255)/256, 256>>>(rpb, rel);
    gemm_kernel<768, 0><<<dim3(6, M_TOK/256), 256, GM_SMEM>>>(x, qkv_w, qkv_b, nullptr);
    attn_kernel<<<BNW*NH, 288, SMEM_ATTN>>>();
    gemm_kernel<256, 1><<<dim3(2, M_TOK/256), 256, GM_SMEM>>>(nullptr, proj_w, proj_b, out);
}

// round 10
// speedup vs baseline: 4.5257x; 1.6227x over previous
#include <cuda_runtime.h>
#include <cuda_fp16.h>
#include <cstdint>

#define NH 8
#define HD 32
#define NWIN 144
#define BNW 2048
#define DIMC 256
#define M_TOK (BNW*NWIN)          // 294912
#define QK_SCALE 0.17677669529663687f

// ---------------- scratch (alloc-free: __device__ globals) ----------------
__device__ __half g_xh[(size_t)M_TOK*DIMC];
__device__ __half g_qh[(size_t)BNW*NH*NWIN*HD];
__device__ __half g_kh[(size_t)BNW*NH*NWIN*HD];
__device__ __half g_vh[(size_t)BNW*NH*NWIN*HD];
__device__ __half g_attn_h[(size_t)M_TOK*DIMC];
__device__ __half g_wqkv[DIMC*3*DIMC];
__device__ __half g_wproj[DIMC*DIMC];
__device__ float  g_bias[NH*NWIN*NWIN];

// ---------------- helpers ----------------
__device__ __forceinline__ uint32_t s2u(const void* p){
    return (uint32_t)__cvta_generic_to_shared(p);
}
__device__ __forceinline__ uint32_t packh2(float lo, float hi){
    __half2 h = __floats2half2_rn(lo, hi);
    return *reinterpret_cast<uint32_t*>(&h);
}
__device__ __forceinline__ void ldsm4(uint32_t* r, uint32_t a){
    asm volatile("ldmatrix.sync.aligned.m8n8.x4.shared.b16 {%0,%1,%2,%3}, [%4];"
      : "=r"(r[0]),"=r"(r[1]),"=r"(r[2]),"=r"(r[3]) : "r"(a));
}
__device__ __forceinline__ void ldsm4t(uint32_t* r, uint32_t a){
    asm volatile("ldmatrix.sync.aligned.m8n8.x4.trans.shared.b16 {%0,%1,%2,%3}, [%4];"
      : "=r"(r[0]),"=r"(r[1]),"=r"(r[2]),"=r"(r[3]) : "r"(a));
}
__device__ __forceinline__ void mma16(float* d, const uint32_t* a, uint32_t b0, uint32_t b1){
    asm volatile(
      "mma.sync.aligned.m16n8k16.row.col.f32.f16.f16.f32 "
      "{%0,%1,%2,%3}, {%4,%5,%6,%7}, {%8,%9}, {%0,%1,%2,%3};\n"
      : "+f"(d[0]), "+f"(d[1]), "+f"(d[2]), "+f"(d[3])
      : "r"(a[0]), "r"(a[1]), "r"(a[2]), "r"(a[3]), "r"(b0), "r"(b1));
}
__device__ __forceinline__ void cp16(uint32_t s, const void* g){
    asm volatile("cp.async.cg.shared.global [%0], [%1], 16;\n" :: "r"(s), "l"(g));
}
#define CP_COMMIT() asm volatile("cp.async.commit_group;\n")
template<int N> __device__ __forceinline__ void cp_wait(){
    asm volatile("cp.async.wait_group %0;\n" :: "n"(N));
}

// ---------------- conversions ----------------
__global__ void convx_kernel(const float* __restrict__ x)
{
    size_t i = (size_t)blockIdx.x * 256 + threadIdx.x;   // one float4
    float4 v = reinterpret_cast<const float4*>(x)[i];
    uint2 o;
    o.x = packh2(v.x, v.y);
    o.y = packh2(v.z, v.w);
    *reinterpret_cast<uint2*>(&g_xh[i*4]) = o;
}
__global__ void convw_kernel(const float* __restrict__ qkv_w, const float* __restrict__ proj_w)
{
    int i = blockIdx.x * 256 + threadIdx.x;              // float4 id, 65536 total
    if (i < 49152) {
        float4 v = reinterpret_cast<const float4*>(qkv_w)[i];
        *reinterpret_cast<uint2*>(&g_wqkv[(size_t)i*4]) = make_uint2(packh2(v.x,v.y), packh2(v.z,v.w));
    } else {
        int j = i - 49152;
        float4 v = reinterpret_cast<const float4*>(proj_w)[j];
        *reinterpret_cast<uint2*>(&g_wproj[(size_t)j*4]) = make_uint2(packh2(v.x,v.y), packh2(v.z,v.w));
    }
}

// ---------------- bias precompute: g_bias[h][r][c] ----------------
__global__ void bias_kernel(const float* __restrict__ rpb, const int* __restrict__ rel)
{
    int i = blockIdx.x * 256 + threadIdx.x;
    if (i < NH*NWIN*NWIN) {
        int h  = i / (NWIN*NWIN);
        int rc = i - h * (NWIN*NWIN);
        g_bias[i] = rpb[rel[rc]*NH + h];
    }
}

// ---------------- fp16 GEMM: C[M,N] = X[M,256] * W[256,N] ----------------
// CTA 256x128, 8 warps (4M x 2N), warp 64x64, BK=32, m16n8k16 HMMA + ldmatrix.
// As [256][40] halves (pad->conflict-free), Bs [32][136] halves.
// 3-stage cp.async, one __syncthreads per K-tile.
#define AS_STR 40
#define BS_STR 136
#define AS_H  (256*AS_STR)            // 10240 halves
#define BS_H  (32*BS_STR)             // 4352 halves
#define GM_STG_H (AS_H + BS_H)        // 14592 halves
#define GM_STG_B (GM_STG_H*2)         // 29184 bytes
#define GM_SMEM  (3*GM_STG_B)         // 87552 bytes

template<int EPI>   // 0: QKV (N=768, scatter), 1: proj (N=256, write out)
__global__ __launch_bounds__(256)
void gemm_kernel(const float* __restrict__ bias, float* __restrict__ out)
{
    extern __shared__ __half smh[];
    const int N_GL = (EPI == 0) ? 768 : 256;
    const __half* X = (EPI == 0) ? g_xh : g_attn_h;
    const __half* W = (EPI == 0) ? g_wqkv : g_wproj;

    const int tid  = threadIdx.x;
    const int warp = tid >> 5, lane = tid & 31;
    const int g    = lane >> 2, tig = lane & 3;
    const int wm   = warp & 3,  wn  = warp >> 2;
    const int bm   = blockIdx.y, bn = blockIdx.x;

    const __half* Xg = X + (size_t)bm * 256 * 256;
    const __half* Wg = W + bn * 128;

    float acc[4][8][4];
    #pragma unroll
    for (int a = 0; a < 4; a++)
      #pragma unroll
      for (int b = 0; b < 8; b++)
        #pragma unroll
        for (int c = 0; c < 4; c++) acc[a][b][c] = 0.f;

    const uint32_t sm_u = s2u(smh);

    // stage loader: A 256x32 halves, B 32x128 halves (16B = 8-half chunks)
    auto stage = [&](int kt, int buf) {
        uint32_t As_u = sm_u + buf * GM_STG_B;
        uint32_t Bs_u = As_u + AS_H*2;
        #pragma unroll
        for (int j = 0; j < 4; j++) {               // 1024 A chunks
            int f = tid + 256*j; int row = f >> 2, c8 = f & 3;
            cp16(As_u + (row*AS_STR + c8*8)*2, Xg + (size_t)row*256 + kt*32 + c8*8);
        }
        #pragma unroll
        for (int j = 0; j < 2; j++) {               // 512 B chunks
            int f = tid + 256*j; int row = f >> 4, c8 = f & 15;
            cp16(Bs_u + (row*BS_STR + c8*8)*2, Wg + (size_t)(kt*32 + row)*N_GL + c8*8);
        }
    };

    // lane-derived ldmatrix offsets (in halves)
    const int a_off = (lane & 15)*AS_STR + (lane >> 4)*8;           // rows rb+(lane&15), k halves
    const int b_off = (lane & 15)*BS_STR + (lane >> 4)*8;           // rows k+(lane&15), col halves

    stage(0, 0); CP_COMMIT();
    stage(1, 1); CP_COMMIT();

    for (int kt = 0; kt < 8; kt++) {        // K = 256 = 8 * 32
        cp_wait<1>();
        __syncthreads();
        if (kt + 2 < 8) { stage(kt+2, (kt+2)%3); CP_COMMIT(); }

        uint32_t As_u = sm_u + (kt%3) * GM_STG_B;
        uint32_t Bs_u = As_u + AS_H*2;

        #pragma unroll
        for (int kk = 0; kk < 2; kk++) {    // 2 x k16
            uint32_t a[4][4];
            #pragma unroll
            for (int mf = 0; mf < 4; mf++) {
                int rb = wm*64 + mf*16;
                ldsm4(a[mf], As_u + (rb*AS_STR + kk*16 + a_off)*2);
            }
            #pragma unroll
            for (int nn = 0; nn < 4; nn++) {
                uint32_t b[4];
                ldsm4t(b, Bs_u + (kk*16*BS_STR + wn*64 + nn*16 + b_off)*2);
                #pragma unroll
                for (int mf = 0; mf < 4; mf++) {
                    mma16(acc[mf][2*nn  ], a[mf], b[0], b[1]);
                    mma16(acc[mf][2*nn+1], a[mf], b[2], b[3]);
                }
            }
        }
    }

    // epilogue
    #pragma unroll
    for (int mf = 0; mf < 4; mf++) {
        #pragma unroll
        for (int half = 0; half < 2; half++) {
            int m = bm*256 + wm*64 + mf*16 + g + half*8;
            int w = m / NWIN;
            int t = m - w * NWIN;
            #pragma unroll
            for (int nf = 0; nf < 8; nf++) {
                int n = bn*128 + wn*64 + nf*8 + 2*tig;
                float2 bb = *(const float2*)(bias + n);
                float v0 = acc[mf][nf][half*2    ] + bb.x;
                float v1 = acc[mf][nf][half*2 + 1] + bb.y;
                if (EPI == 0) {
                    int sec = n >> 8, c = n & 255, h = c >> 5, d = c & 31;
                    __half* dst = (sec == 0) ? g_qh : ((sec == 1) ? g_kh : g_vh);
                    if (sec == 0) { v0 *= QK_SCALE; v1 *= QK_SCALE; }
                    *(uint32_t*)&dst[(((w*NH + h)*NWIN + t) << 5) + d] = packh2(v0, v1);
                } else {
                    *(float2*)&out[(size_t)m*DIMC + n] = make_float2(v0, v1);
                }
            }
        }
    }
}

// ---------------- attention: one CTA per (window, head), 9 warps ----------------
// fp16 m16n8k16. Warp owns one 16-row tile. Softmax in registers; the S C-frag
// col-pairs ARE the O A-frag k-pairs -> one half2 pack, no shfl, no P smem.
#define AT_STR 40
#define SMEM_ATTN (3*NWIN*AT_STR*2)   // 34560 B

__global__ __launch_bounds__(288, 2)
void attn_kernel()
{
    extern __shared__ __half smA[];
    __half* Qs = smA;
    __half* Ks = Qs + NWIN*AT_STR;
    __half* Vs = Ks + NWIN*AT_STR;

    const int tid  = threadIdx.x;
    const int warp = tid >> 5, lane = tid & 31;
    const int g    = lane >> 2, tig = lane & 3;
    const int w    = blockIdx.x >> 3;
    const int h    = blockIdx.x & 7;

    const size_t base = ((size_t)(w*NH + h)) * NWIN * HD;
    #pragma unroll
    for (int it = 0; it < 2; it++) {
        int c = tid + it*288;               // 576 chunks of 8 halves
        int row = c >> 2, c8 = (c & 3)*8;
        uint4 q = *(const uint4*)(g_qh + base + (size_t)c*8);
        uint4 k = *(const uint4*)(g_kh + base + (size_t)c*8);
        uint4 v = *(const uint4*)(g_vh + base + (size_t)c*8);
        *(uint4*)&Qs[row*AT_STR + c8] = q;
        *(uint4*)&Ks[row*AT_STR + c8] = k;
        *(uint4*)&Vs[row*AT_STR + c8] = v;
    }
    __syncthreads();

    const int r0 = warp * 16;
    const uint32_t Qs_u = s2u(Qs), Ks_u = s2u(Ks), Vs_u = s2u(Vs);

    // ldmatrix lane offsets (halves)
    const int a_off  = (lane & 15)*AT_STR + (lane >> 4)*8;                       // A / trans-B pattern
    const int k_off  = ((lane & 7) + ((lane >> 4) << 3))*AT_STR + ((lane >> 3) & 1)*8; // K non-trans

    // ---- S = Q K^T (16 x 144 per warp) ----
    float acc[18][4];
    #pragma unroll
    for (int nf = 0; nf < 18; nf++)
        #pragma unroll
        for (int i = 0; i < 4; i++) acc[nf][i] = 0.f;

    uint32_t qa[2][4];
    ldsm4(qa[0], Qs_u + (r0*AT_STR +  0 + a_off)*2);
    ldsm4(qa[1], Qs_u + (r0*AT_STR + 16 + a_off)*2);

    #pragma unroll
    for (int nn = 0; nn < 9; nn++) {
        #pragma unroll
        for (int kk = 0; kk < 2; kk++) {
            uint32_t kb[4];
            ldsm4(kb, Ks_u + (nn*16*AT_STR + kk*16 + k_off)*2);
            mma16(acc[2*nn  ], qa[kk], kb[0], kb[1]);
            mma16(acc[2*nn+1], qa[kk], kb[2], kb[3]);
        }
    }

    // ---- bias add + register softmax ----
    const float* biash = g_bias + h*NWIN*NWIN;
    float mx0 = -1e30f, mx1 = -1e30f;
    #pragma unroll
    for (int nf = 0; nf < 18; nf++) {
        float2 b0 = *(const float2*)(biash + (r0+g  )*NWIN + nf*8 + 2*tig);
        float2 b1 = *(const float2*)(biash + (r0+g+8)*NWIN + nf*8 + 2*tig);
        acc[nf][0] += b0.x; acc[nf][1] += b0.y;
        acc[nf][2] += b1.x; acc[nf][3] += b1.y;
        mx0 = fmaxf(mx0, fmaxf(acc[nf][0], acc[nf][1]));
        mx1 = fmaxf(mx1, fmaxf(acc[nf][2], acc[nf][3]));
    }
    mx0 = fmaxf(mx0, __shfl_xor_sync(0xffffffffu, mx0, 1));
    mx0 = fmaxf(mx0, __shfl_xor_sync(0xffffffffu, mx0, 2));
    mx1 = fmaxf(mx1, __shfl_xor_sync(0xffffffffu, mx1, 1));
    mx1 = fmaxf(mx1, __shfl_xor_sync(0xffffffffu, mx1, 2));

    float s0 = 0.f, s1 = 0.f;
    uint32_t pk[18][2];
    #pragma unroll
    for (int nf = 0; nf < 18; nf++) {
        float e0 = __expf(acc[nf][0] - mx0);
        float e1 = __expf(acc[nf][1] - mx0);
        float e2 = __expf(acc[nf][2] - mx1);
        float e3 = __expf(acc[nf][3] - mx1);
        s0 += e0 + e1; s1 += e2 + e3;
        pk[nf][0] = packh2(e0, e1);       // row g,   k-pair (2tig, 2tig+1)
        pk[nf][1] = packh2(e2, e3);       // row g+8, k-pair
    }
    s0 += __shfl_xor_sync(0xffffffffu, s0, 1);
    s0 += __shfl_xor_sync(0xffffffffu, s0, 2);
    s1 += __shfl_xor_sync(0xffffffffu, s1, 1);
    s1 += __shfl_xor_sync(0xffffffffu, s1, 2);
    float inv0 = 1.0f / s0, inv1 = 1.0f / s1;

    // ---- O = P V (16 x 32 per warp) ----
    float o[4][4];
    #pragma unroll
    for (int nf = 0; nf < 4; nf++)
        #pragma unroll
        for (int i = 0; i < 4; i++) o[nf][i] = 0.f;

    #pragma unroll
    for (int ks = 0; ks < 9; ks++) {
        uint32_t a[4] = { pk[2*ks][0], pk[2*ks][1], pk[2*ks+1][0], pk[2*ks+1][1] };
        #pragma unroll
        for (int nd = 0; nd < 2; nd++) {
            uint32_t vb[4];
            ldsm4t(vb, Vs_u + (ks*16*AT_STR + nd*16 + a_off)*2);
            mma16(o[2*nd  ], a, vb[0], vb[1]);
            mma16(o[2*nd+1], a, vb[2], vb[3]);
        }
    }

    const size_t obase = ((size_t)w * NWIN) * DIMC + h*HD;
    #pragma unroll
    for (int nf = 0; nf < 4; nf++) {
        int d = nf*8 + 2*tig;
        *(uint32_t*)&g_attn_h[obase + (size_t)(r0+g  )*DIMC + d] = packh2(o[nf][0]*inv0, o[nf][1]*inv0);
        *(uint32_t*)&g_attn_h[obase + (size_t)(r0+g+8)*DIMC + d] = packh2(o[nf][2]*inv1, o[nf][3]*inv1);
    }
}

// ---------------- launch ----------------
extern "C" void kernel_launch(void* const* d_in, const int* in_sizes, int n_in,
                              void* d_out, int out_size)
{
    const float* x      = (const float*)d_in[0];
    const float* qkv_w  = (const float*)d_in[1];
    const float* qkv_b  = (const float*)d_in[2];
    const float* proj_w = (const float*)d_in[3];
    const float* proj_b = (const float*)d_in[4];
    const float* rpb    = (const float*)d_in[5];
    const int*   rel    = (const int*)d_in[6];
    float*       out    = (float*)d_out;

    cudaFuncSetAttribute(gemm_kernel<0>, cudaFuncAttributeMaxDynamicSharedMemorySize, GM_SMEM);
    cudaFuncSetAttribute(gemm_kernel<1>, cudaFuncAttributeMaxDynamicSharedMemorySize, GM_SMEM);
    cudaFuncSetAttribute(attn_kernel, cudaFuncAttributeMaxDynamicSharedMemorySize, SMEM_ATTN);

    convx_kernel<<<73728, 256>>>(x);
    convw_kernel<<<256, 256>>>(qkv_w, proj_w);
    bias_kernel<<<(NH*NWIN*NWIN + 255)/256, 256>>>(rpb, rel);
    gemm_kernel<0><<<dim3(6, M_TOK/256), 256, GM_SMEM>>>(qkv_b, nullptr);
    attn_kernel<<<BNW*NH, 288, SMEM_ATTN>>>();
    gemm_kernel<1><<<dim3(2, M_TOK/256), 256, GM_SMEM>>>(proj_b, out);
}

// round 11
// speedup vs baseline: 5.2313x; 1.1559x over previous
#include <cuda_runtime.h>
#include <cuda_fp16.h>
#include <cstdint>

#define NH 8
#define HD 32
#define NWIN 144
#define BNW 2048
#define DIMC 256
#define M_TOK (BNW*NWIN)          // 294912
#define QK_SCALE 0.17677669529663687f

// ---------------- scratch (alloc-free: __device__ globals) ----------------
__device__ __half g_xh[(size_t)M_TOK*DIMC];
__device__ __half g_qh[(size_t)BNW*NH*NWIN*HD];
__device__ __half g_kh[(size_t)BNW*NH*NWIN*HD];
__device__ __half g_vh[(size_t)BNW*NH*NWIN*HD];
__device__ __half g_attn_h[(size_t)M_TOK*DIMC];
__device__ __half g_wqkv[DIMC*3*DIMC];
__device__ __half g_wproj[DIMC*DIMC];
__device__ float  g_bias[NH*NWIN*NWIN];

// ---------------- helpers ----------------
__device__ __forceinline__ uint32_t s2u(const void* p){
    return (uint32_t)__cvta_generic_to_shared(p);
}
__device__ __forceinline__ uint32_t packh2(float lo, float hi){
    __half2 h = __floats2half2_rn(lo, hi);
    return *reinterpret_cast<uint32_t*>(&h);
}
__device__ __forceinline__ void ldsm4(uint32_t* r, uint32_t a){
    asm volatile("ldmatrix.sync.aligned.m8n8.x4.shared.b16 {%0,%1,%2,%3}, [%4];"
      : "=r"(r[0]),"=r"(r[1]),"=r"(r[2]),"=r"(r[3]) : "r"(a));
}
__device__ __forceinline__ void ldsm4t(uint32_t* r, uint32_t a){
    asm volatile("ldmatrix.sync.aligned.m8n8.x4.trans.shared.b16 {%0,%1,%2,%3}, [%4];"
      : "=r"(r[0]),"=r"(r[1]),"=r"(r[2]),"=r"(r[3]) : "r"(a));
}
__device__ __forceinline__ void mma16(float* d, const uint32_t* a, uint32_t b0, uint32_t b1){
    asm volatile(
      "mma.sync.aligned.m16n8k16.row.col.f32.f16.f16.f32 "
      "{%0,%1,%2,%3}, {%4,%5,%6,%7}, {%8,%9}, {%0,%1,%2,%3};\n"
      : "+f"(d[0]), "+f"(d[1]), "+f"(d[2]), "+f"(d[3])
      : "r"(a[0]), "r"(a[1]), "r"(a[2]), "r"(a[3]), "r"(b0), "r"(b1));
}
__device__ __forceinline__ void cp16(uint32_t s, const void* g){
    asm volatile("cp.async.cg.shared.global [%0], [%1], 16;\n" :: "r"(s), "l"(g));
}
#define CP_COMMIT() asm volatile("cp.async.commit_group;\n")
template<int N> __device__ __forceinline__ void cp_wait(){
    asm volatile("cp.async.wait_group %0;\n" :: "n"(N));
}

// ---------------- conversions ----------------
__global__ void convx_kernel(const float* __restrict__ x)
{
    size_t i = (size_t)blockIdx.x * 256 + threadIdx.x;   // one float4
    float4 v = reinterpret_cast<const float4*>(x)[i];
    uint2 o;
    o.x = packh2(v.x, v.y);
    o.y = packh2(v.z, v.w);
    *reinterpret_cast<uint2*>(&g_xh[i*4]) = o;
}
__global__ void convw_kernel(const float* __restrict__ qkv_w, const float* __restrict__ proj_w)
{
    int i = blockIdx.x * 256 + threadIdx.x;              // float4 id, 65536 total
    if (i < 49152) {
        float4 v = reinterpret_cast<const float4*>(qkv_w)[i];
        *reinterpret_cast<uint2*>(&g_wqkv[(size_t)i*4]) = make_uint2(packh2(v.x,v.y), packh2(v.z,v.w));
    } else {
        int j = i - 49152;
        float4 v = reinterpret_cast<const float4*>(proj_w)[j];
        *reinterpret_cast<uint2*>(&g_wproj[(size_t)j*4]) = make_uint2(packh2(v.x,v.y), packh2(v.z,v.w));
    }
}

// ---------------- bias precompute: g_bias[h][r][c] ----------------
__global__ void bias_kernel(const float* __restrict__ rpb, const int* __restrict__ rel)
{
    int i = blockIdx.x * 256 + threadIdx.x;
    if (i < NH*NWIN*NWIN) {
        int h  = i / (NWIN*NWIN);
        int rc = i - h * (NWIN*NWIN);
        g_bias[i] = rpb[rel[rc]*NH + h];
    }
}

// ---------------- fp16 GEMM: C[M,N] = X[M,256] * W[256,N] ----------------
// CTA 64x128, 128 threads (4 warps, 1M x 4N), warp tile 64x32, BK=32.
// m16n8k16 HMMA + ldmatrix, 3-stage cp.async, ONE barrier per K-tile.
// 3 CTAs/SM (regs<=170, smem 41.5KB) -> 12 warps/SM, independent barriers.
#define AS_STR 40
#define BS_STR 136
#define AS_H  (64*AS_STR)             // 2560 halves
#define BS_H  (32*BS_STR)             // 4352 halves
#define GM_STG_H (AS_H + BS_H)        // 6912 halves
#define GM_STG_B (GM_STG_H*2)         // 13824 bytes
#define GM_SMEM  (3*GM_STG_B)         // 41472 bytes

template<int EPI>   // 0: QKV (N=768, scatter), 1: proj (N=256, write out)
__global__ __launch_bounds__(128, 3)
void gemm_kernel(const float* __restrict__ bias, float* __restrict__ out)
{
    extern __shared__ __half smh[];
    const int N_GL = (EPI == 0) ? 768 : 256;
    const __half* X = (EPI == 0) ? g_xh : g_attn_h;
    const __half* W = (EPI == 0) ? g_wqkv : g_wproj;

    const int tid  = threadIdx.x;
    const int warp = tid >> 5, lane = tid & 31;
    const int g    = lane >> 2, tig = lane & 3;
    const int bm   = blockIdx.y, bn = blockIdx.x;

    const __half* Xg = X + (size_t)bm * 64 * 256;
    const __half* Wg = W + bn * 128;

    float acc[4][4][4];
    #pragma unroll
    for (int a = 0; a < 4; a++)
      #pragma unroll
      for (int b = 0; b < 4; b++)
        #pragma unroll
        for (int c = 0; c < 4; c++) acc[a][b][c] = 0.f;

    const uint32_t sm_u = s2u(smh);

    // stage loader: A 64x32 halves, B 32x128 halves (16B = 8-half chunks)
    auto stage = [&](int kt, int buf) {
        uint32_t As_u = sm_u + buf * GM_STG_B;
        uint32_t Bs_u = As_u + AS_H*2;
        #pragma unroll
        for (int j = 0; j < 2; j++) {               // 256 A chunks
            int f = tid + 128*j; int row = f >> 2, c8 = f & 3;
            cp16(As_u + (row*AS_STR + c8*8)*2, Xg + (size_t)row*256 + kt*32 + c8*8);
        }
        #pragma unroll
        for (int j = 0; j < 4; j++) {               // 512 B chunks
            int f = tid + 128*j; int row = f >> 4, c8 = f & 15;
            cp16(Bs_u + (row*BS_STR + c8*8)*2, Wg + (size_t)(kt*32 + row)*N_GL + c8*8);
        }
    };

    const int a_off = (lane & 15)*AS_STR + (lane >> 4)*8;
    const int b_off = (lane & 15)*BS_STR + (lane >> 4)*8;

    stage(0, 0); CP_COMMIT();
    stage(1, 1); CP_COMMIT();

    for (int kt = 0; kt < 8; kt++) {        // K = 256 = 8 * 32
        if (kt < 7) cp_wait<1>(); else cp_wait<0>();
        __syncthreads();
        if (kt + 2 < 8) { stage(kt+2, (kt+2)%3); CP_COMMIT(); }

        uint32_t As_u = sm_u + (kt%3) * GM_STG_B;
        uint32_t Bs_u = As_u + AS_H*2;

        #pragma unroll
        for (int kk = 0; kk < 2; kk++) {    // 2 x k16
            uint32_t a[4][4];
            #pragma unroll
            for (int mf = 0; mf < 4; mf++)
                ldsm4(a[mf], As_u + (mf*16*AS_STR + kk*16 + a_off)*2);
            #pragma unroll
            for (int nn = 0; nn < 2; nn++) {
                uint32_t b[4];
                ldsm4t(b, Bs_u + (kk*16*BS_STR + warp*32 + nn*16 + b_off)*2);
                #pragma unroll
                for (int mf = 0; mf < 4; mf++) {
                    mma16(acc[mf][2*nn  ], a[mf], b[0], b[1]);
                    mma16(acc[mf][2*nn+1], a[mf], b[2], b[3]);
                }
            }
        }
    }

    // epilogue
    #pragma unroll
    for (int mf = 0; mf < 4; mf++) {
        #pragma unroll
        for (int half = 0; half < 2; half++) {
            int m = bm*64 + mf*16 + g + half*8;
            int w = m / NWIN;
            int t = m - w * NWIN;
            #pragma unroll
            for (int nf = 0; nf < 4; nf++) {
                int n = bn*128 + warp*32 + nf*8 + 2*tig;
                float2 bb = *(const float2*)(bias + n);
                float v0 = acc[mf][nf][half*2    ] + bb.x;
                float v1 = acc[mf][nf][half*2 + 1] + bb.y;
                if (EPI == 0) {
                    int sec = n >> 8, c = n & 255, h = c >> 5, d = c & 31;
                    __half* dst = (sec == 0) ? g_qh : ((sec == 1) ? g_kh : g_vh);
                    if (sec == 0) { v0 *= QK_SCALE; v1 *= QK_SCALE; }
                    *(uint32_t*)&dst[(((w*NH + h)*NWIN + t) << 5) + d] = packh2(v0, v1);
                } else {
                    *(float2*)&out[(size_t)m*DIMC + n] = make_float2(v0, v1);
                }
            }
        }
    }
}

// ---------------- attention: one CTA per (window, head), 9 warps ----------------
// fp16 m16n8k16. Warp owns one 16-row tile. Softmax in registers; packed P
// stored back INTO acc slots (no pk array -> no spills under (288,2) cap).
#define AT_STR 40
#define SMEM_ATTN (3*NWIN*AT_STR*2)   // 34560 B

__global__ __launch_bounds__(288, 2)
void attn_kernel()
{
    extern __shared__ __half smA[];
    __half* Qs = smA;
    __half* Ks = Qs + NWIN*AT_STR;
    __half* Vs = Ks + NWIN*AT_STR;

    const int tid  = threadIdx.x;
    const int warp = tid >> 5, lane = tid & 31;
    const int g    = lane >> 2, tig = lane & 3;
    const int w    = blockIdx.x >> 3;
    const int h    = blockIdx.x & 7;

    const size_t base = ((size_t)(w*NH + h)) * NWIN * HD;
    #pragma unroll
    for (int it = 0; it < 2; it++) {
        int c = tid + it*288;               // 576 chunks of 8 halves
        int row = c >> 2, c8 = (c & 3)*8;
        uint4 q = *(const uint4*)(g_qh + base + (size_t)c*8);
        uint4 k = *(const uint4*)(g_kh + base + (size_t)c*8);
        uint4 v = *(const uint4*)(g_vh + base + (size_t)c*8);
        *(uint4*)&Qs[row*AT_STR + c8] = q;
        *(uint4*)&Ks[row*AT_STR + c8] = k;
        *(uint4*)&Vs[row*AT_STR + c8] = v;
    }
    __syncthreads();

    const int r0 = warp * 16;
    const uint32_t Qs_u = s2u(Qs), Ks_u = s2u(Ks), Vs_u = s2u(Vs);

    const int a_off  = (lane & 15)*AT_STR + (lane >> 4)*8;                       // A / trans-B pattern
    const int k_off  = ((lane & 7) + ((lane >> 4) << 3))*AT_STR + ((lane >> 3) & 1)*8; // K non-trans

    // ---- S = Q K^T (16 x 144 per warp) ----
    float acc[18][4];
    #pragma unroll
    for (int nf = 0; nf < 18; nf++)
        #pragma unroll
        for (int i = 0; i < 4; i++) acc[nf][i] = 0.f;

    uint32_t qa[2][4];
    ldsm4(qa[0], Qs_u + (r0*AT_STR +  0 + a_off)*2);
    ldsm4(qa[1], Qs_u + (r0*AT_STR + 16 + a_off)*2);

    #pragma unroll
    for (int nn = 0; nn < 9; nn++) {
        #pragma unroll
        for (int kk = 0; kk < 2; kk++) {
            uint32_t kb[4];
            ldsm4(kb, Ks_u + (nn*16*AT_STR + kk*16 + k_off)*2);
            mma16(acc[2*nn  ], qa[kk], kb[0], kb[1]);
            mma16(acc[2*nn+1], qa[kk], kb[2], kb[3]);
        }
    }

    // ---- bias add + register softmax ----
    const float* biash = g_bias + h*NWIN*NWIN;
    float mx0 = -1e30f, mx1 = -1e30f;
    #pragma unroll
    for (int nf = 0; nf < 18; nf++) {
        float2 b0 = *(const float2*)(biash + (r0+g  )*NWIN + nf*8 + 2*tig);
        float2 b1 = *(const float2*)(biash + (r0+g+8)*NWIN + nf*8 + 2*tig);
        acc[nf][0] += b0.x; acc[nf][1] += b0.y;
        acc[nf][2] += b1.x; acc[nf][3] += b1.y;
        mx0 = fmaxf(mx0, fmaxf(acc[nf][0], acc[nf][1]));
        mx1 = fmaxf(mx1, fmaxf(acc[nf][2], acc[nf][3]));
    }
    mx0 = fmaxf(mx0, __shfl_xor_sync(0xffffffffu, mx0, 1));
    mx0 = fmaxf(mx0, __shfl_xor_sync(0xffffffffu, mx0, 2));
    mx1 = fmaxf(mx1, __shfl_xor_sync(0xffffffffu, mx1, 1));
    mx1 = fmaxf(mx1, __shfl_xor_sync(0xffffffffu, mx1, 2));

    float s0 = 0.f, s1 = 0.f;
    #pragma unroll
    for (int nf = 0; nf < 18; nf++) {
        float e0 = __expf(acc[nf][0] - mx0);
        float e1 = __expf(acc[nf][1] - mx0);
        float e2 = __expf(acc[nf][2] - mx1);
        float e3 = __expf(acc[nf][3] - mx1);
        s0 += e0 + e1; s1 += e2 + e3;
        acc[nf][0] = __uint_as_float(packh2(e0, e1));   // row g   k-pair, reuse acc
        acc[nf][1] = __uint_as_float(packh2(e2, e3));   // row g+8 k-pair
    }
    s0 += __shfl_xor_sync(0xffffffffu, s0, 1);
    s0 += __shfl_xor_sync(0xffffffffu, s0, 2);
    s1 += __shfl_xor_sync(0xffffffffu, s1, 1);
    s1 += __shfl_xor_sync(0xffffffffu, s1, 2);
    float inv0 = 1.0f / s0, inv1 = 1.0f / s1;

    // ---- O = P V (16 x 32 per warp) ----
    float o[4][4];
    #pragma unroll
    for (int nf = 0; nf < 4; nf++)
        #pragma unroll
        for (int i = 0; i < 4; i++) o[nf][i] = 0.f;

    #pragma unroll
    for (int ks = 0; ks < 9; ks++) {
        uint32_t a[4] = { __float_as_uint(acc[2*ks  ][0]), __float_as_uint(acc[2*ks  ][1]),
                          __float_as_uint(acc[2*ks+1][0]), __float_as_uint(acc[2*ks+1][1]) };
        #pragma unroll
        for (int nd = 0; nd < 2; nd++) {
            uint32_t vb[4];
            ldsm4t(vb, Vs_u + (ks*16*AT_STR + nd*16 + a_off)*2);
            mma16(o[2*nd  ], a, vb[0], vb[1]);
            mma16(o[2*nd+1], a, vb[2], vb[3]);
        }
    }

    const size_t obase = ((size_t)w * NWIN) * DIMC + h*HD;
    #pragma unroll
    for (int nf = 0; nf < 4; nf++) {
        int d = nf*8 + 2*tig;
        *(uint32_t*)&g_attn_h[obase + (size_t)(r0+g  )*DIMC + d] = packh2(o[nf][0]*inv0, o[nf][1]*inv0);
        *(uint32_t*)&g_attn_h[obase + (size_t)(r0+g+8)*DIMC + d] = packh2(o[nf][2]*inv1, o[nf][3]*inv1);
    }
}

// ---------------- launch ----------------
extern "C" void kernel_launch(void* const* d_in, const int* in_sizes, int n_in,
                              void* d_out, int out_size)
{
    const float* x      = (const float*)d_in[0];
    const float* qkv_w  = (const float*)d_in[1];
    const float* qkv_b  = (const float*)d_in[2];
    const float* proj_w = (const float*)d_in[3];
    const float* proj_b = (const float*)d_in[4];
    const float* rpb    = (const float*)d_in[5];
    const int*   rel    = (const int*)d_in[6];
    float*       out    = (float*)d_out;

    cudaFuncSetAttribute(gemm_kernel<0>, cudaFuncAttributeMaxDynamicSharedMemorySize, GM_SMEM);
    cudaFuncSetAttribute(gemm_kernel<1>, cudaFuncAttributeMaxDynamicSharedMemorySize, GM_SMEM);
    cudaFuncSetAttribute(attn_kernel, cudaFuncAttributeMaxDynamicSharedMemorySize, SMEM_ATTN);

    convx_kernel<<<73728, 256>>>(x);
    convw_kernel<<<256, 256>>>(qkv_w, proj_w);
    bias_kernel<<<(NH*NWIN*NWIN + 255)/256, 256>>>(rpb, rel);
    gemm_kernel<0><<<dim3(6, M_TOK/64), 128, GM_SMEM>>>(qkv_b, nullptr);
    attn_kernel<<<BNW*NH, 288, SMEM_ATTN>>>();
    gemm_kernel<1><<<dim3(2, M_TOK/64), 128, GM_SMEM>>>(proj_b, out);
}

// round 14
// speedup vs baseline: 5.5071x; 1.0527x over previous
#include <cuda_runtime.h>
#include <cuda_fp16.h>
#include <cstdint>

#define NH 8
#define HD 32
#define NWIN 144
#define BNW 2048
#define DIMC 256
#define M_TOK (BNW*NWIN)          // 294912
#define QK_SCALE 0.17677669529663687f

// ---------------- scratch (alloc-free: __device__ globals) ----------------
__device__ __half g_xh[(size_t)M_TOK*DIMC];
__device__ __half g_qh[(size_t)BNW*NH*NWIN*HD];
__device__ __half g_kh[(size_t)BNW*NH*NWIN*HD];
__device__ __half g_vh[(size_t)BNW*NH*NWIN*HD];
__device__ __half g_attn_h[(size_t)M_TOK*DIMC];
__device__ __half g_wqkv[DIMC*3*DIMC];
__device__ __half g_wproj[DIMC*DIMC];
__device__ __half g_bias_h[NH*NWIN*NWIN];

// ---------------- helpers ----------------
__device__ __forceinline__ uint32_t s2u(const void* p){
    return (uint32_t)__cvta_generic_to_shared(p);
}
__device__ __forceinline__ uint32_t packh2(float lo, float hi){
    __half2 h = __floats2half2_rn(lo, hi);
    return *reinterpret_cast<uint32_t*>(&h);
}
__device__ __forceinline__ void ldsm4(uint32_t* r, uint32_t a){
    asm volatile("ldmatrix.sync.aligned.m8n8.x4.shared.b16 {%0,%1,%2,%3}, [%4];"
      : "=r"(r[0]),"=r"(r[1]),"=r"(r[2]),"=r"(r[3]) : "r"(a));
}
__device__ __forceinline__ void ldsm4t(uint32_t* r, uint32_t a){
    asm volatile("ldmatrix.sync.aligned.m8n8.x4.trans.shared.b16 {%0,%1,%2,%3}, [%4];"
      : "=r"(r[0]),"=r"(r[1]),"=r"(r[2]),"=r"(r[3]) : "r"(a));
}
__device__ __forceinline__ void mma16(float* d, const uint32_t* a, uint32_t b0, uint32_t b1){
    asm volatile(
      "mma.sync.aligned.m16n8k16.row.col.f32.f16.f16.f32 "
      "{%0,%1,%2,%3}, {%4,%5,%6,%7}, {%8,%9}, {%0,%1,%2,%3};\n"
      : "+f"(d[0]), "+f"(d[1]), "+f"(d[2]), "+f"(d[3])
      : "r"(a[0]), "r"(a[1]), "r"(a[2]), "r"(a[3]), "r"(b0), "r"(b1));
}
__device__ __forceinline__ void cp16(uint32_t s, const void* g){
    asm volatile("cp.async.cg.shared.global [%0], [%1], 16;\n" :: "r"(s), "l"(g));
}
#define CP_COMMIT() asm volatile("cp.async.commit_group;\n")
template<int N> __device__ __forceinline__ void cp_wait(){
    asm volatile("cp.async.wait_group %0;\n" :: "n"(N));
}

// ---------------- conversions ----------------
__global__ void convx_kernel(const float* __restrict__ x)
{
    size_t i = (size_t)blockIdx.x * 256 + threadIdx.x;   // one float4
    float4 v = reinterpret_cast<const float4*>(x)[i];
    uint2 o;
    o.x = packh2(v.x, v.y);
    o.y = packh2(v.z, v.w);
    *reinterpret_cast<uint2*>(&g_xh[i*4]) = o;
}
__global__ void convw_kernel(const float* __restrict__ qkv_w, const float* __restrict__ proj_w)
{
    int i = blockIdx.x * 256 + threadIdx.x;              // float4 id, 65536 total
    if (i < 49152) {
        float4 v = reinterpret_cast<const float4*>(qkv_w)[i];
        *reinterpret_cast<uint2*>(&g_wqkv[(size_t)i*4]) = make_uint2(packh2(v.x,v.y), packh2(v.z,v.w));
    } else {
        int j = i - 49152;
        float4 v = reinterpret_cast<const float4*>(proj_w)[j];
        *reinterpret_cast<uint2*>(&g_wproj[(size_t)j*4]) = make_uint2(packh2(v.x,v.y), packh2(v.z,v.w));
    }
}

// ---------------- bias precompute: g_bias_h[h][r][c] (fp16) ----------------
__global__ void bias_kernel(const float* __restrict__ rpb, const int* __restrict__ rel)
{
    int i = blockIdx.x * 256 + threadIdx.x;
    if (i < NH*NWIN*NWIN) {
        int h  = i / (NWIN*NWIN);
        int rc = i - h * (NWIN*NWIN);
        g_bias_h[i] = __float2half(rpb[rel[rc]*NH + h]);
    }
}

// ---------------- fp16 GEMM: C[M,N] = X[M,256] * W[256,N] ----------------
// CTA 128x128, 256 threads (8 warps: 2M x 4N), warp tile 64x32, BK=32.
// m16n8k16 HMMA + ldmatrix, 3-stage cp.async, ONE barrier per K-tile.
// 2 CTAs/SM -> 16 warps/SM; L2 traffic 128KB/CTA (33% less than 64x128 tiling).
#define AS_STR 40
#define BS_STR 136
#define AS_H  (128*AS_STR)            // 5120 halves
#define BS_H  (32*BS_STR)             // 4352 halves
#define GM_STG_H (AS_H + BS_H)        // 9472 halves
#define GM_STG_B (GM_STG_H*2)         // 18944 bytes
#define GM_SMEM  (3*GM_STG_B)         // 56832 bytes

template<int EPI>   // 0: QKV (N=768, scatter), 1: proj (N=256, write out)
__global__ __launch_bounds__(256, 2)
void gemm_kernel(const float* __restrict__ bias, float* __restrict__ out)
{
    extern __shared__ __half smh[];
    const int N_GL = (EPI == 0) ? 768 : 256;
    const __half* X = (EPI == 0) ? g_xh : g_attn_h;
    const __half* W = (EPI == 0) ? g_wqkv : g_wproj;

    const int tid  = threadIdx.x;
    const int warp = tid >> 5, lane = tid & 31;
    const int g    = lane >> 2, tig = lane & 3;
    const int wm   = warp & 1,  wn  = warp >> 1;
    const int bm   = blockIdx.y, bn = blockIdx.x;

    const __half* Xg = X + (size_t)bm * 128 * 256;
    const __half* Wg = W + bn * 128;

    float acc[4][4][4];
    #pragma unroll
    for (int a = 0; a < 4; a++)
      #pragma unroll
      for (int b = 0; b < 4; b++)
        #pragma unroll
        for (int c = 0; c < 4; c++) acc[a][b][c] = 0.f;

    const uint32_t sm_u = s2u(smh);

    // stage loader: A 128x32 halves, B 32x128 halves (16B = 8-half chunks)
    auto stage = [&](int kt, int buf) {
        uint32_t As_u = sm_u + buf * GM_STG_B;
        uint32_t Bs_u = As_u + AS_H*2;
        #pragma unroll
        for (int j = 0; j < 2; j++) {               // 512 A chunks
            int f = tid + 256*j; int row = f >> 2, c8 = f & 3;
            cp16(As_u + (row*AS_STR + c8*8)*2, Xg + (size_t)row*256 + kt*32 + c8*8);
        }
        #pragma unroll
        for (int j = 0; j < 2; j++) {               // 512 B chunks
            int f = tid + 256*j; int row = f >> 4, c8 = f & 15;
            cp16(Bs_u + (row*BS_STR + c8*8)*2, Wg + (size_t)(kt*32 + row)*N_GL + c8*8);
        }
    };

    const int a_off = (lane & 15)*AS_STR + (lane >> 4)*8;
    const int b_off = (lane & 15)*BS_STR + (lane >> 4)*8;

    stage(0, 0); CP_COMMIT();
    stage(1, 1); CP_COMMIT();

    for (int kt = 0; kt < 8; kt++) {        // K = 256 = 8 * 32
        if (kt < 7) cp_wait<1>(); else cp_wait<0>();
        __syncthreads();
        if (kt + 2 < 8) { stage(kt+2, (kt+2)%3); CP_COMMIT(); }

        uint32_t As_u = sm_u + (kt%3) * GM_STG_B;
        uint32_t Bs_u = As_u + AS_H*2;

        #pragma unroll
        for (int kk = 0; kk < 2; kk++) {    // 2 x k16
            uint32_t a[4][4];
            #pragma unroll
            for (int mf = 0; mf < 4; mf++)
                ldsm4(a[mf], As_u + ((wm*64 + mf*16)*AS_STR + kk*16 + a_off)*2);
            #pragma unroll
            for (int nn = 0; nn < 2; nn++) {
                uint32_t b[4];
                ldsm4t(b, Bs_u + (kk*16*BS_STR + wn*32 + nn*16 + b_off)*2);
                #pragma unroll
                for (int mf = 0; mf < 4; mf++) {
                    mma16(acc[mf][2*nn  ], a[mf], b[0], b[1]);
                    mma16(acc[mf][2*nn+1], a[mf], b[2], b[3]);
                }
            }
        }
    }

    // epilogue
    #pragma unroll
    for (int mf = 0; mf < 4; mf++) {
        #pragma unroll
        for (int half = 0; half < 2; half++) {
            int m = bm*128 + wm*64 + mf*16 + g + half*8;
            int w = m / NWIN;
            int t = m - w * NWIN;
            #pragma unroll
            for (int nf = 0; nf < 4; nf++) {
                int n = bn*128 + wn*32 + nf*8 + 2*tig;
                float2 bb = *(const float2*)(bias + n);
                float v0 = acc[mf][nf][half*2    ] + bb.x;
                float v1 = acc[mf][nf][half*2 + 1] + bb.y;
                if (EPI == 0) {
                    int sec = n >> 8, c = n & 255, h = c >> 5, d = c & 31;
                    __half* dst = (sec == 0) ? g_qh : ((sec == 1) ? g_kh : g_vh);
                    if (sec == 0) { v0 *= QK_SCALE; v1 *= QK_SCALE; }
                    *(uint32_t*)&dst[(((w*NH + h)*NWIN + t) << 5) + d] = packh2(v0, v1);
                } else {
                    *(float2*)&out[(size_t)m*DIMC + n] = make_float2(v0, v1);
                }
            }
        }
    }
}

// ---------------- attention: one CTA per (window, head), 9 warps ----------------
// fp16 m16n8k16. Warp owns one 16-row tile. Softmax in registers; packed P
// stored back INTO acc slots. Bias now fp16 (half2 loads, half the L2 bytes).
#define AT_STR 40
#define SMEM_ATTN (3*NWIN*AT_STR*2)   // 34560 B

__global__ __launch_bounds__(288, 2)
void attn_kernel()
{
    extern __shared__ __half smA[];
    __half* Qs = smA;
    __half* Ks = Qs + NWIN*AT_STR;
    __half* Vs = Ks + NWIN*AT_STR;

    const int tid  = threadIdx.x;
    const int warp = tid >> 5, lane = tid & 31;
    const int g    = lane >> 2, tig = lane & 3;
    const int w    = blockIdx.x >> 3;
    const int h    = blockIdx.x & 7;

    const size_t base = ((size_t)(w*NH + h)) * NWIN * HD;
    #pragma unroll
    for (int it = 0; it < 2; it++) {
        int c = tid + it*288;               // 576 chunks of 8 halves
        int row = c >> 2, c8 = (c & 3)*8;
        uint4 q = *(const uint4*)(g_qh + base + (size_t)c*8);
        uint4 k = *(const uint4*)(g_kh + base + (size_t)c*8);
        uint4 v = *(const uint4*)(g_vh + base + (size_t)c*8);
        *(uint4*)&Qs[row*AT_STR + c8] = q;
        *(uint4*)&Ks[row*AT_STR + c8] = k;
        *(uint4*)&Vs[row*AT_STR + c8] = v;
    }
    __syncthreads();

    const int r0 = warp * 16;
    const uint32_t Qs_u = s2u(Qs), Ks_u = s2u(Ks), Vs_u = s2u(Vs);

    const int a_off  = (lane & 15)*AT_STR + (lane >> 4)*8;
    const int k_off  = ((lane & 7) + ((lane >> 4) << 3))*AT_STR + ((lane >> 3) & 1)*8;

    // ---- S = Q K^T (16 x 144 per warp) ----
    float acc[18][4];
    #pragma unroll
    for (int nf = 0; nf < 18; nf++)
        #pragma unroll
        for (int i = 0; i < 4; i++) acc[nf][i] = 0.f;

    uint32_t qa[2][4];
    ldsm4(qa[0], Qs_u + (r0*AT_STR +  0 + a_off)*2);
    ldsm4(qa[1], Qs_u + (r0*AT_STR + 16 + a_off)*2);

    #pragma unroll
    for (int nn = 0; nn < 9; nn++) {
        #pragma unroll
        for (int kk = 0; kk < 2; kk++) {
            uint32_t kb[4];
            ldsm4(kb, Ks_u + (nn*16*AT_STR + kk*16 + k_off)*2);
            mma16(acc[2*nn  ], qa[kk], kb[0], kb[1]);
            mma16(acc[2*nn+1], qa[kk], kb[2], kb[3]);
        }
    }

    // ---- bias add (fp16 table) + register softmax ----
    const __half* biash = g_bias_h + h*NWIN*NWIN;
    float mx0 = -1e30f, mx1 = -1e30f;
    #pragma unroll
    for (int nf = 0; nf < 18; nf++) {
        float2 b0 = __half22float2(*(const __half2*)(biash + (r0+g  )*NWIN + nf*8 + 2*tig));
        float2 b1 = __half22float2(*(const __half2*)(biash + (r0+g+8)*NWIN + nf*8 + 2*tig));
        acc[nf][0] += b0.x; acc[nf][1] += b0.y;
        acc[nf][2] += b1.x; acc[nf][3] += b1.y;
        mx0 = fmaxf(mx0, fmaxf(acc[nf][0], acc[nf][1]));
        mx1 = fmaxf(mx1, fmaxf(acc[nf][2], acc[nf][3]));
    }
    mx0 = fmaxf(mx0, __shfl_xor_sync(0xffffffffu, mx0, 1));
    mx0 = fmaxf(mx0, __shfl_xor_sync(0xffffffffu, mx0, 2));
    mx1 = fmaxf(mx1, __shfl_xor_sync(0xffffffffu, mx1, 1));
    mx1 = fmaxf(mx1, __shfl_xor_sync(0xffffffffu, mx1, 2));

    float s0 = 0.f, s1 = 0.f;
    #pragma unroll
    for (int nf = 0; nf < 18; nf++) {
        float e0 = __expf(acc[nf][0] - mx0);
        float e1 = __expf(acc[nf][1] - mx0);
        float e2 = __expf(acc[nf][2] - mx1);
        float e3 = __expf(acc[nf][3] - mx1);
        s0 += e0 + e1; s1 += e2 + e3;
        acc[nf][0] = __uint_as_float(packh2(e0, e1));   // row g   k-pair, reuse acc
        acc[nf][1] = __uint_as_float(packh2(e2, e3));   // row g+8 k-pair
    }
    s0 += __shfl_xor_sync(0xffffffffu, s0, 1);
    s0 += __shfl_xor_sync(0xffffffffu, s0, 2);
    s1 += __shfl_xor_sync(0xffffffffu, s1, 1);
    s1 += __shfl_xor_sync(0xffffffffu, s1, 2);
    float inv0 = 1.0f / s0, inv1 = 1.0f / s1;

    // ---- O = P V (16 x 32 per warp) ----
    float o[4][4];
    #pragma unroll
    for (int nf = 0; nf < 4; nf++)
        #pragma unroll
        for (int i = 0; i < 4; i++) o[nf][i] = 0.f;

    #pragma unroll
    for (int ks = 0; ks < 9; ks++) {
        uint32_t a[4] = { __float_as_uint(acc[2*ks  ][0]), __float_as_uint(acc[2*ks  ][1]),
                          __float_as_uint(acc[2*ks+1][0]), __float_as_uint(acc[2*ks+1][1]) };
        #pragma unroll
        for (int nd = 0; nd < 2; nd++) {
            uint32_t vb[4];
            ldsm4t(vb, Vs_u + (ks*16*AT_STR + nd*16 + a_off)*2);
            mma16(o[2*nd  ], a, vb[0], vb[1]);
            mma16(o[2*nd+1], a, vb[2], vb[3]);
        }
    }

    const size_t obase = ((size_t)w * NWIN) * DIMC + h*HD;
    #pragma unroll
    for (int nf = 0; nf < 4; nf++) {
        int d = nf*8 + 2*tig;
        *(uint32_t*)&g_attn_h[obase + (size_t)(r0+g  )*DIMC + d] = packh2(o[nf][0]*inv0, o[nf][1]*inv0);
        *(uint32_t*)&g_attn_h[obase + (size_t)(r0+g+8)*DIMC + d] = packh2(o[nf][2]*inv1, o[nf][3]*inv1);
    }
}

// ---------------- launch ----------------
extern "C" void kernel_launch(void* const* d_in, const int* in_sizes, int n_in,
                              void* d_out, int out_size)
{
    const float* x      = (const float*)d_in[0];
    const float* qkv_w  = (const float*)d_in[1];
    const float* qkv_b  = (const float*)d_in[2];
    const float* proj_w = (const float*)d_in[3];
    const float* proj_b = (const float*)d_in[4];
    const float* rpb    = (const float*)d_in[5];
    const int*   rel    = (const int*)d_in[6];
    float*       out    = (float*)d_out;

    cudaFuncSetAttribute(gemm_kernel<0>, cudaFuncAttributeMaxDynamicSharedMemorySize, GM_SMEM);
    cudaFuncSetAttribute(gemm_kernel<1>, cudaFuncAttributeMaxDynamicSharedMemorySize, GM_SMEM);
    cudaFuncSetAttribute(attn_kernel, cudaFuncAttributeMaxDynamicSharedMemorySize, SMEM_ATTN);

    convx_kernel<<<73728, 256>>>(x);
    convw_kernel<<<256, 256>>>(qkv_w, proj_w);
    bias_kernel<<<(NH*NWIN*NWIN + 255)/256, 256>>>(rpb, rel);
    gemm_kernel<0><<<dim3(6, M_TOK/128), 256, GM_SMEM>>>(qkv_b, nullptr);
    attn_kernel<<<BNW*NH, 288, SMEM_ATTN>>>();
    gemm_kernel<1><<<dim3(2, M_TOK/128), 256, GM_SMEM>>>(proj_b, out);
}

// round 17
// speedup vs baseline: 5.6172x; 1.0200x over previous
#include <cuda_runtime.h>
#include <cuda_fp16.h>
#include <cstdint>

#define NH 8
#define HD 32
#define NWIN 144
#define BNW 2048
#define DIMC 256
#define M_TOK (BNW*NWIN)          // 294912
// QK scale with log2(e) folded in: attention works in log2 domain, exp -> ex2
#define QK_SCALE_L2 (0.17677669529663687f * 1.4426950408889634f)
#define LOG2E 1.4426950408889634f

// ---------------- scratch (alloc-free: __device__ globals) ----------------
__device__ __half g_xh[(size_t)M_TOK*DIMC];
__device__ __half g_qh[(size_t)BNW*NH*NWIN*HD];
__device__ __half g_kh[(size_t)BNW*NH*NWIN*HD];
__device__ __half g_vh[(size_t)BNW*NH*NWIN*HD];
__device__ __half g_attn_h[(size_t)M_TOK*DIMC];
__device__ __half g_wqkv[DIMC*3*DIMC];
__device__ __half g_wproj[DIMC*DIMC];
__device__ __half g_bias_h[NH*NWIN*NWIN];   // pre-scaled by log2(e)

// ---------------- helpers ----------------
__device__ __forceinline__ uint32_t s2u(const void* p){
    return (uint32_t)__cvta_generic_to_shared(p);
}
__device__ __forceinline__ uint32_t packh2(float lo, float hi){
    __half2 h = __floats2half2_rn(lo, hi);
    return *reinterpret_cast<uint32_t*>(&h);
}
__device__ __forceinline__ void ldsm4(uint32_t* r, uint32_t a){
    asm volatile("ldmatrix.sync.aligned.m8n8.x4.shared.b16 {%0,%1,%2,%3}, [%4];"
      : "=r"(r[0]),"=r"(r[1]),"=r"(r[2]),"=r"(r[3]) : "r"(a));
}
__device__ __forceinline__ void ldsm4t(uint32_t* r, uint32_t a){
    asm volatile("ldmatrix.sync.aligned.m8n8.x4.trans.shared.b16 {%0,%1,%2,%3}, [%4];"
      : "=r"(r[0]),"=r"(r[1]),"=r"(r[2]),"=r"(r[3]) : "r"(a));
}
__device__ __forceinline__ void mma16(float* d, const uint32_t* a, uint32_t b0, uint32_t b1){
    asm volatile(
      "mma.sync.aligned.m16n8k16.row.col.f32.f16.f16.f32 "
      "{%0,%1,%2,%3}, {%4,%5,%6,%7}, {%8,%9}, {%0,%1,%2,%3};\n"
      : "+f"(d[0]), "+f"(d[1]), "+f"(d[2]), "+f"(d[3])
      : "r"(a[0]), "r"(a[1]), "r"(a[2]), "r"(a[3]), "r"(b0), "r"(b1));
}
__device__ __forceinline__ void cp16(uint32_t s, const void* g){
    asm volatile("cp.async.cg.shared.global [%0], [%1], 16;\n" :: "r"(s), "l"(g));
}
#define CP_COMMIT() asm volatile("cp.async.commit_group;\n")
template<int N> __device__ __forceinline__ void cp_wait(){
    asm volatile("cp.async.wait_group %0;\n" :: "n"(N));
}

// ---------------- merged prep: x->fp16, W->fp16, bias table (log2-scaled) ----------------
__global__ void prep_kernel(const float* __restrict__ x,
                            const float* __restrict__ qkv_w,
                            const float* __restrict__ proj_w,
                            const float* __restrict__ rpb,
                            const int*   __restrict__ rel)
{
    int b = blockIdx.x, tid = threadIdx.x;
    if (b < 73728) {
        size_t i = (size_t)b * 256 + tid;
        float4 v = reinterpret_cast<const float4*>(x)[i];
        *reinterpret_cast<uint2*>(&g_xh[i*4]) = make_uint2(packh2(v.x,v.y), packh2(v.z,v.w));
    } else if (b < 73728 + 256) {
        int i = (b - 73728) * 256 + tid;
        if (i < 49152) {
            float4 v = reinterpret_cast<const float4*>(qkv_w)[i];
            *reinterpret_cast<uint2*>(&g_wqkv[(size_t)i*4]) = make_uint2(packh2(v.x,v.y), packh2(v.z,v.w));
        } else {
            int j = i - 49152;
            float4 v = reinterpret_cast<const float4*>(proj_w)[j];
            *reinterpret_cast<uint2*>(&g_wproj[(size_t)j*4]) = make_uint2(packh2(v.x,v.y), packh2(v.z,v.w));
        }
    } else {
        int i = (b - 73984) * 256 + tid;
        if (i < NH*NWIN*NWIN) {
            int h  = i / (NWIN*NWIN);
            int rc = i - h * (NWIN*NWIN);
            g_bias_h[i] = __float2half(rpb[rel[rc]*NH + h] * LOG2E);
        }
    }
}

// ---------------- fp16 GEMM: C[M,N] = X[M,256] * W[256,N] ----------------
// CTA: 256 threads (8 warps: 2M x 4N), M-tile 128 RESIDENT in smem (80KB,
// loaded once), bn loops over full N (6 cols of 128 for QKV, 2 for proj).
// B streamed in 8.7KB stages, 3-deep cp.async pipeline, 1 barrier per K-tile.
// L2 traffic: A once + W x (M/128)  (~1.06 GB for QKV vs 2.7 GB before).
#define A_RES_H (8*128*40)            // 40960 halves = 80 KB (8 k-chunks, stride 40)
#define BSTG_H  (32*136)              // 4352 halves = 8704 B
#define GM_SMEM ((A_RES_H + 3*BSTG_H)*2)   // 108032 B

template<int EPI>   // 0: QKV (NB=6, scatter q/k/v), 1: proj (NB=2, fp32 out)
__global__ __launch_bounds__(256, 2)
void gemm_kernel(const float* __restrict__ bias, float* __restrict__ out)
{
    extern __shared__ __half smh[];
    const int NB   = (EPI == 0) ? 6 : 2;
    const int N_GL = (EPI == 0) ? 768 : 256;
    const __half* X = (EPI == 0) ? g_xh : g_attn_h;
    const __half* W = (EPI == 0) ? g_wqkv : g_wproj;

    const int tid  = threadIdx.x;
    const int warp = tid >> 5, lane = tid & 31;
    const int g    = lane >> 2, tig = lane & 3;
    const int wm   = warp & 1,  wn  = warp >> 1;
    const int bm   = blockIdx.x;

    const __half* Xg = X + (size_t)bm * 128 * 256;
    const uint32_t A_u = s2u(smh);
    const uint32_t B_u = A_u + A_RES_H*2;

    // ---- load entire A tile 128x256 once (8 k-chunks of [128][40]) ----
    #pragma unroll
    for (int j = 0; j < 16; j++) {
        int f = tid + 256*j;              // 4096 chunks of 8 halves
        int row = f >> 5, c8 = f & 31;
        int kt = c8 >> 2, c = c8 & 3;
        cp16(A_u + (kt*5120 + row*40 + c*8)*2, Xg + (size_t)row*256 + c8*8);
    }
    CP_COMMIT();

    // B stage loader: global stage s = bn*8 + kt -> buffer s%3
    auto loadB = [&](int s) {
        int bnn = s >> 3, kt = s & 7;
        const __half* Wg = W + (size_t)(kt*32)*N_GL + bnn*128;
        uint32_t Bs = B_u + (s%3)*BSTG_H*2;
        #pragma unroll
        for (int j = 0; j < 2; j++) {
            int f = tid + 256*j;          // 512 chunks
            int row = f >> 4, c8 = f & 15;
            cp16(Bs + (row*136 + c8*8)*2, Wg + (size_t)row*N_GL + c8*8);
        }
    };

    loadB(0); CP_COMMIT();
    loadB(1); CP_COMMIT();

    const int a_off = (lane & 15)*40  + (lane >> 4)*8;
    const int b_off = (lane & 15)*136 + (lane >> 4)*8;
    const int L = NB*8;

    for (int bn = 0; bn < NB; bn++) {
        float acc[4][4][4];
        #pragma unroll
        for (int a = 0; a < 4; a++)
          #pragma unroll
          for (int b = 0; b < 4; b++)
            #pragma unroll
            for (int c = 0; c < 4; c++) acc[a][b][c] = 0.f;

        for (int kt = 0; kt < 8; kt++) {
            int s = bn*8 + kt;
            if (s == L-1) cp_wait<0>(); else cp_wait<1>();
            __syncthreads();
            if (s + 2 < L) { loadB(s+2); CP_COMMIT(); }

            uint32_t Bs = B_u + (s%3)*BSTG_H*2;
            #pragma unroll
            for (int kk = 0; kk < 2; kk++) {
                uint32_t a[4][4];
                #pragma unroll
                for (int mf = 0; mf < 4; mf++)
                    ldsm4(a[mf], A_u + (kt*5120 + (wm*64 + mf*16)*40 + kk*16 + a_off)*2);
                #pragma unroll
                for (int nn = 0; nn < 2; nn++) {
                    uint32_t b[4];
                    ldsm4t(b, Bs + (kk*16*136 + wn*32 + nn*16 + b_off)*2);
                    #pragma unroll
                    for (int mf = 0; mf < 4; mf++) {
                        mma16(acc[mf][2*nn  ], a[mf], b[0], b[1]);
                        mma16(acc[mf][2*nn+1], a[mf], b[2], b[3]);
                    }
                }
            }
        }

        // ---- epilogue for this bn ----
        #pragma unroll
        for (int mf = 0; mf < 4; mf++) {
            #pragma unroll
            for (int half = 0; half < 2; half++) {
                int m = bm*128 + wm*64 + mf*16 + g + half*8;
                int w = m / NWIN;
                int t = m - w * NWIN;
                #pragma unroll
                for (int nf = 0; nf < 4; nf++) {
                    int n = bn*128 + wn*32 + nf*8 + 2*tig;
                    float2 bb = *(const float2*)(bias + n);
                    float v0 = acc[mf][nf][half*2    ] + bb.x;
                    float v1 = acc[mf][nf][half*2 + 1] + bb.y;
                    if (EPI == 0) {
                        int sec = n >> 8, c = n & 255, h = c >> 5, d = c & 31;
                        __half* dst = (sec == 0) ? g_qh : ((sec == 1) ? g_kh : g_vh);
                        if (sec == 0) { v0 *= QK_SCALE_L2; v1 *= QK_SCALE_L2; }
                        *(uint32_t*)&dst[(((w*NH + h)*NWIN + t) << 5) + d] = packh2(v0, v1);
                    } else {
                        *(float2*)&out[(size_t)m*DIMC + n] = make_float2(v0, v1);
                    }
                }
            }
        }
    }
}

// ---------------- attention: one CTA per (window, head), 9 warps ----------------
// fp16 m16n8k16. Scores are in log2 domain (Q and bias pre-scaled by log2e):
// softmax exp via ONE ex2.approx.f16x2 per column-pair, result already packed
// as the PV A-fragment. Softmax fully in registers, P never touches smem.
#define AT_STR 40
#define SMEM_ATTN (3*NWIN*AT_STR*2)   // 34560 B

__global__ __launch_bounds__(288, 2)
void attn_kernel()
{
    extern __shared__ __half smA[];
    __half* Qs = smA;
    __half* Ks = Qs + NWIN*AT_STR;
    __half* Vs = Ks + NWIN*AT_STR;

    const int tid  = threadIdx.x;
    const int warp = tid >> 5, lane = tid & 31;
    const int g    = lane >> 2, tig = lane & 3;
    const int w    = blockIdx.x >> 3;
    const int h    = blockIdx.x & 7;

    const size_t base = ((size_t)(w*NH + h)) * NWIN * HD;
    #pragma unroll
    for (int it = 0; it < 2; it++) {
        int c = tid + it*288;               // 576 chunks of 8 halves
        int row = c >> 2, c8 = (c & 3)*8;
        uint4 q = *(const uint4*)(g_qh + base + (size_t)c*8);
        uint4 k = *(const uint4*)(g_kh + base + (size_t)c*8);
        uint4 v = *(const uint4*)(g_vh + base + (size_t)c*8);
        *(uint4*)&Qs[row*AT_STR + c8] = q;
        *(uint4*)&Ks[row*AT_STR + c8] = k;
        *(uint4*)&Vs[row*AT_STR + c8] = v;
    }
    __syncthreads();

    const int r0 = warp * 16;
    const uint32_t Qs_u = s2u(Qs), Ks_u = s2u(Ks), Vs_u = s2u(Vs);

    const int a_off  = (lane & 15)*AT_STR + (lane >> 4)*8;
    const int k_off  = ((lane & 7) + ((lane >> 4) << 3))*AT_STR + ((lane >> 3) & 1)*8;

    // ---- S = Q K^T (16 x 144 per warp), log2-domain scores ----
    float acc[18][4];
    #pragma unroll
    for (int nf = 0; nf < 18; nf++)
        #pragma unroll
        for (int i = 0; i < 4; i++) acc[nf][i] = 0.f;

    uint32_t qa[2][4];
    ldsm4(qa[0], Qs_u + (r0*AT_STR +  0 + a_off)*2);
    ldsm4(qa[1], Qs_u + (r0*AT_STR + 16 + a_off)*2);

    #pragma unroll
    for (int nn = 0; nn < 9; nn++) {
        #pragma unroll
        for (int kk = 0; kk < 2; kk++) {
            uint32_t kb[4];
            ldsm4(kb, Ks_u + (nn*16*AT_STR + kk*16 + k_off)*2);
            mma16(acc[2*nn  ], qa[kk], kb[0], kb[1]);
            mma16(acc[2*nn+1], qa[kk], kb[2], kb[3]);
        }
    }

    // ---- bias add + max (log2 domain) ----
    const __half* biash = g_bias_h + h*NWIN*NWIN;
    float mx0 = -1e30f, mx1 = -1e30f;
    #pragma unroll
    for (int nf = 0; nf < 18; nf++) {
        float2 b0 = __half22float2(*(const __half2*)(biash + (r0+g  )*NWIN + nf*8 + 2*tig));
        float2 b1 = __half22float2(*(const __half2*)(biash + (r0+g+8)*NWIN + nf*8 + 2*tig));
        acc[nf][0] += b0.x; acc[nf][1] += b0.y;
        acc[nf][2] += b1.x; acc[nf][3] += b1.y;
        mx0 = fmaxf(mx0, fmaxf(acc[nf][0], acc[nf][1]));
        mx1 = fmaxf(mx1, fmaxf(acc[nf][2], acc[nf][3]));
    }
    mx0 = fmaxf(mx0, __shfl_xor_sync(0xffffffffu, mx0, 1));
    mx0 = fmaxf(mx0, __shfl_xor_sync(0xffffffffu, mx0, 2));
    mx1 = fmaxf(mx1, __shfl_xor_sync(0xffffffffu, mx1, 1));
    mx1 = fmaxf(mx1, __shfl_xor_sync(0xffffffffu, mx1, 2));

    // ---- P = 2^(s - m) via ex2.f16x2 (one MUFU per pair, packed output) ----
    float s0 = 0.f, s1 = 0.f;
    #pragma unroll
    for (int nf = 0; nf < 18; nf++) {
        uint32_t p0 = packh2(acc[nf][0] - mx0, acc[nf][1] - mx0);
        uint32_t p1 = packh2(acc[nf][2] - mx1, acc[nf][3] - mx1);
        asm("ex2.approx.f16x2 %0, %1;" : "=r"(p0) : "r"(p0));
        asm("ex2.approx.f16x2 %0, %1;" : "=r"(p1) : "r"(p1));
        float2 f0 = __half22float2(*(const __half2*)&p0);
        float2 f1 = __half22float2(*(const __half2*)&p1);
        s0 += f0.x + f0.y;
        s1 += f1.x + f1.y;
        acc[nf][0] = __uint_as_float(p0);   // row g   k-pair (packed fp16)
        acc[nf][1] = __uint_as_float(p1);   // row g+8 k-pair
    }
    s0 += __shfl_xor_sync(0xffffffffu, s0, 1);
    s0 += __shfl_xor_sync(0xffffffffu, s0, 2);
    s1 += __shfl_xor_sync(0xffffffffu, s1, 1);
    s1 += __shfl_xor_sync(0xffffffffu, s1, 2);
    float inv0 = 1.0f / s0, inv1 = 1.0f / s1;

    // ---- O = P V (16 x 32 per warp) ----
    float o[4][4];
    #pragma unroll
    for (int nf = 0; nf < 4; nf++)
        #pragma unroll
        for (int i = 0; i < 4; i++) o[nf][i] = 0.f;

    #pragma unroll
    for (int ks = 0; ks < 9; ks++) {
        uint32_t a[4] = { __float_as_uint(acc[2*ks  ][0]), __float_as_uint(acc[2*ks  ][1]),
                          __float_as_uint(acc[2*ks+1][0]), __float_as_uint(acc[2*ks+1][1]) };
        #pragma unroll
        for (int nd = 0; nd < 2; nd++) {
            uint32_t vb[4];
            ldsm4t(vb, Vs_u + (ks*16*AT_STR + nd*16 + a_off)*2);
            mma16(o[2*nd  ], a, vb[0], vb[1]);
            mma16(o[2*nd+1], a, vb[2], vb[3]);
        }
    }

    const size_t obase = ((size_t)w * NWIN) * DIMC + h*HD;
    #pragma unroll
    for (int nf = 0; nf < 4; nf++) {
        int d = nf*8 + 2*tig;
        *(uint32_t*)&g_attn_h[obase + (size_t)(r0+g  )*DIMC + d] = packh2(o[nf][0]*inv0, o[nf][1]*inv0);
        *(uint32_t*)&g_attn_h[obase + (size_t)(r0+g+8)*DIMC + d] = packh2(o[nf][2]*inv1, o[nf][3]*inv1);
    }
}

// ---------------- launch ----------------
extern "C" void kernel_launch(void* const* d_in, const int* in_sizes, int n_in,
                              void* d_out, int out_size)
{
    const float* x      = (const float*)d_in[0];
    const float* qkv_w  = (const float*)d_in[1];
    const float* qkv_b  = (const float*)d_in[2];
    const float* proj_w = (const float*)d_in[3];
    const float* proj_b = (const float*)d_in[4];
    const float* rpb    = (const float*)d_in[5];
    const int*   rel    = (const int*)d_in[6];
    float*       out    = (float*)d_out;

    cudaFuncSetAttribute(gemm_kernel<0>, cudaFuncAttributeMaxDynamicSharedMemorySize, GM_SMEM);
    cudaFuncSetAttribute(gemm_kernel<1>, cudaFuncAttributeMaxDynamicSharedMemorySize, GM_SMEM);
    cudaFuncSetAttribute(attn_kernel, cudaFuncAttributeMaxDynamicSharedMemorySize, SMEM_ATTN);

    prep_kernel<<<73728 + 256 + 648, 256>>>(x, qkv_w, proj_w, rpb, rel);
    gemm_kernel<0><<<M_TOK/128, 256, GM_SMEM>>>(qkv_b, nullptr);
    attn_kernel<<<BNW*NH, 288, SMEM_ATTN>>>();
    gemm_kernel<1><<<M_TOK/128, 256, GM_SMEM>>>(proj_b, out);
}